// round 1
// baseline (speedup 1.0000x reference)
#include <cuda_runtime.h>
#include <math.h>

#define Dq   768
#define Gq   2048
#define Bq   128
#define NEGq 15

// Static scratch (allocation-free rule): ~120 MB total.
__device__ float g_xw[(size_t)36864 * Dq];     // xw = x @ W_sfa^T  (N rows used)
__device__ float g_pooled[(size_t)Gq * Dq];    // pooled [G, D]
__device__ float g_part[(size_t)Gq * 24];      // per (group, n-block) MLP partial sums
__device__ int   g_off[Gq];                    // exclusive prefix of group sizes

// ---------------------------------------------------------------------------
// K0: offsets (prefix sum of 2048 sizes)
// ---------------------------------------------------------------------------
__global__ void k0_offsets(const int* __restrict__ sizes) {
    __shared__ int part[256];
    __shared__ int base[256];
    int tid = threadIdx.x;
    int loc[8];
    int ssum = 0;
#pragma unroll
    for (int i = 0; i < 8; i++) { loc[i] = ssum; ssum += sizes[tid * 8 + i]; }
    part[tid] = ssum;
    __syncthreads();
    if (tid == 0) {
        int run = 0;
        for (int i = 0; i < 256; i++) { int v = part[i]; base[i] = run; run += v; }
    }
    __syncthreads();
    int b0 = base[tid];
#pragma unroll
    for (int i = 0; i < 8; i++) g_off[tid * 8 + i] = b0 + loc[i];
}

// ---------------------------------------------------------------------------
// Shared 128x128x8 fp32 GEMM mainloop (C = A[M,K] @ B[Nn,K]^T), NT layout.
// 256 threads, 8x8 per-thread tile split 2x2 (4-wide groups 64 apart) for
// conflict-free LDS.128 reads. Accumulates into acc[8][8].
// ---------------------------------------------------------------------------
__device__ __forceinline__ void gemm_tile_128x128(
    const float* __restrict__ A, const float* __restrict__ Bm,
    int M, int K, int bm, int bn, int tid,
    float (*As)[128], float (*Bs)[128], float acc[8][8])
{
    int lr = tid >> 1;
    int lc = (tid & 1) << 2;
    int ar = bm + lr; if (ar >= M) ar = M - 1;   // clamp (M is a multiple of 128 in practice)
    const float* Ap = A  + (size_t)ar * K + lc;
    const float* Bp = Bm + (size_t)(bn + lr) * K + lc;
    int ty = tid >> 4, tx = tid & 15;
    for (int k0 = 0; k0 < K; k0 += 8) {
        float4 av = *(const float4*)(Ap + k0);
        float4 bv = *(const float4*)(Bp + k0);
        As[lc + 0][lr] = av.x; As[lc + 1][lr] = av.y; As[lc + 2][lr] = av.z; As[lc + 3][lr] = av.w;
        Bs[lc + 0][lr] = bv.x; Bs[lc + 1][lr] = bv.y; Bs[lc + 2][lr] = bv.z; Bs[lc + 3][lr] = bv.w;
        __syncthreads();
#pragma unroll
        for (int k = 0; k < 8; k++) {
            float4 a0 = *(const float4*)&As[k][ty * 4];
            float4 a1 = *(const float4*)&As[k][64 + ty * 4];
            float4 b0 = *(const float4*)&Bs[k][tx * 4];
            float4 b1 = *(const float4*)&Bs[k][64 + tx * 4];
            float ra[8] = {a0.x, a0.y, a0.z, a0.w, a1.x, a1.y, a1.z, a1.w};
            float rb[8] = {b0.x, b0.y, b0.z, b0.w, b1.x, b1.y, b1.z, b1.w};
#pragma unroll
            for (int i = 0; i < 8; i++)
#pragma unroll
                for (int j = 0; j < 8; j++)
                    acc[i][j] = fmaf(ra[i], rb[j], acc[i][j]);
        }
        __syncthreads();
    }
}

// ---------------------------------------------------------------------------
// K1: g_xw[n,e] = sum_d x[n,d] * W_sfa[e,d]   (M=N, Nn=768, K=768)
// ---------------------------------------------------------------------------
__global__ __launch_bounds__(256) void k1_xw_gemm(
    const float* __restrict__ A, const float* __restrict__ W, int M)
{
    __shared__ float As[8][128];
    __shared__ float Bs[8][128];
    float acc[8][8] = {};
    int bm = blockIdx.y * 128, bn = blockIdx.x * 128;
    int tid = threadIdx.x;
    gemm_tile_128x128(A, W, M, Dq, bm, bn, tid, As, Bs, acc);
    int ty = tid >> 4, tx = tid & 15;
#pragma unroll
    for (int i = 0; i < 8; i++) {
        int r = bm + ((i < 4) ? (ty * 4 + i) : (64 + ty * 4 + i - 4));
        if (r < M) {
            *(float4*)(g_xw + (size_t)r * Dq + bn + tx * 4) =
                make_float4(acc[i][0], acc[i][1], acc[i][2], acc[i][3]);
            *(float4*)(g_xw + (size_t)r * Dq + bn + 64 + tx * 4) =
                make_float4(acc[i][4], acc[i][5], acc[i][6], acc[i][7]);
        }
    }
}

// ---------------------------------------------------------------------------
// K2: per-group attention + pooling. One block per group.
// x rows and xw rows (transposed: xwT[d][m], m contiguous -> conflict-free)
// staged in dynamic SMEM. 2x2 register tiles for the s x s score matrix.
// ---------------------------------------------------------------------------
#define XS_STR 772   // 768 + 4 padding floats per row (float4-aligned)

__global__ __launch_bounds__(256) void k2_attention(
    const float* __restrict__ x, const int* __restrict__ sizes)
{
    extern __shared__ float sm[];
    float* xs  = sm;                      // [32][772]
    float* xwT = sm + 32 * XS_STR;        // [768][33]
    float* S   = xwT + 768 * 33;          // [32][33]
    float* att = S + 32 * 33;             // [32]

    int g = blockIdx.x;
    int s = sizes[g];
    int base = g_off[g];
    int tid = threadIdx.x;

    const float4* xg = (const float4*)(x    + (size_t)base * Dq);
    const float4* wg = (const float4*)(g_xw + (size_t)base * Dq);
    int tot4 = s * (Dq / 4);
    for (int i = tid; i < tot4; i += 256) {
        int row = i / 192, d4 = i - row * 192;
        float4 v = xg[i];
        *(float4*)(xs + row * XS_STR + d4 * 4) = v;
        float4 w = wg[i];
        int d = d4 * 4;
        xwT[(d + 0) * 33 + row] = w.x;
        xwT[(d + 1) * 33 + row] = w.y;
        xwT[(d + 2) * 33 + row] = w.z;
        xwT[(d + 3) * 33 + row] = w.w;
    }
    __syncthreads();

    int ty = tid >> 4, tx = tid & 15;
    int l0 = ty * 2, m0 = tx * 2;
    if (l0 < s && m0 < s) {
        float a00 = 0.f, a01 = 0.f, a10 = 0.f, a11 = 0.f;
        const float* xr0 = xs + l0 * XS_STR;
        const float* xr1 = xs + (l0 + 1) * XS_STR;   // row <= 31, always in-bounds SMEM
#pragma unroll 8
        for (int d = 0; d < Dq; d++) {
            float w0 = xwT[d * 33 + m0];
            float w1 = xwT[d * 33 + m0 + 1];
            float p0 = xr0[d];
            float p1 = xr1[d];
            a00 = fmaf(p0, w0, a00); a01 = fmaf(p0, w1, a01);
            a10 = fmaf(p1, w0, a10); a11 = fmaf(p1, w1, a11);
        }
        S[l0 * 33 + m0] = tanhf(a00);
        if (m0 + 1 < s) S[l0 * 33 + m0 + 1] = tanhf(a01);
        if (l0 + 1 < s) {
            S[(l0 + 1) * 33 + m0] = tanhf(a10);
            if (m0 + 1 < s) S[(l0 + 1) * 33 + m0 + 1] = tanhf(a11);
        }
    }
    __syncthreads();

    // column max over l, then softmax over m (warp 0)
    if (tid < 32) {
        int m = tid;
        float mx = -INFINITY;
        if (m < s)
            for (int l = 0; l < s; l++) mx = fmaxf(mx, S[l * 33 + m]);
        float wm = mx;
#pragma unroll
        for (int o = 16; o > 0; o >>= 1) wm = fmaxf(wm, __shfl_xor_sync(0xffffffffu, wm, o));
        float e = (m < s) ? expf(mx - wm) : 0.f;
        float se = e;
#pragma unroll
        for (int o = 16; o > 0; o >>= 1) se += __shfl_xor_sync(0xffffffffu, se, o);
        att[m] = e / se;
    }
    __syncthreads();

    // pooled[d] = sum_m att[m] * x[m,d]
    float* outp = g_pooled + (size_t)g * Dq;
    for (int d = tid; d < Dq; d += 256) {
        float a = 0.f;
        for (int m = 0; m < s; m++) a = fmaf(att[m], xs[m * XS_STR + d], a);
        outp[d] = a;
    }
}

// ---------------------------------------------------------------------------
// K3: fused MLP GEMM. H = pooled @ W1^T (never materialized); epilogue does
// relu(H + b1) * W2 and writes per-(row, n-block) partial sums (deterministic,
// no atomics). M=2048, Nn=3072, K=768, grid (24, 16).
// ---------------------------------------------------------------------------
__global__ __launch_bounds__(256) void k3_mlp(
    const float* __restrict__ W1, const float* __restrict__ b1v,
    const float* __restrict__ W2)
{
    __shared__ float As[8][128];
    __shared__ float Bs[8][128];
    float acc[8][8] = {};
    int bm = blockIdx.y * 128, bn = blockIdx.x * 128;
    int tid = threadIdx.x;
    gemm_tile_128x128(g_pooled, W1, Gq, Dq, bm, bn, tid, As, Bs, acc);

    int ty = tid >> 4, tx = tid & 15;
    int c0 = bn + tx * 4, c1 = bn + 64 + tx * 4;
    float bb[8], ww[8];
#pragma unroll
    for (int j = 0; j < 4; j++) {
        bb[j]     = b1v[c0 + j]; ww[j]     = W2[c0 + j];
        bb[4 + j] = b1v[c1 + j]; ww[4 + j] = W2[c1 + j];
    }
    float part[8];
#pragma unroll
    for (int i = 0; i < 8; i++) {
        float p = 0.f;
#pragma unroll
        for (int j = 0; j < 8; j++) {
            float h = acc[i][j] + bb[j];
            p = fmaf(fmaxf(h, 0.f), ww[j], p);
        }
        part[i] = p;
    }
    // reduce across the 16 tx lanes (same rows), width-16 shfl segments
#pragma unroll
    for (int off = 8; off > 0; off >>= 1)
#pragma unroll
        for (int i = 0; i < 8; i++)
            part[i] += __shfl_down_sync(0xffffffffu, part[i], off, 16);
    if (tx == 0) {
#pragma unroll
        for (int i = 0; i < 8; i++) {
            int r = bm + ((i < 4) ? (ty * 4 + i) : (64 + ty * 4 + i - 4));
            g_part[(size_t)r * 24 + blockIdx.x] = part[i];
        }
    }
}

// ---------------------------------------------------------------------------
// K4: scores = sigmoid(sum(parts) + b2); margin-ranking loss reduction.
// ---------------------------------------------------------------------------
__global__ void k4_loss(const float* __restrict__ b2, float* __restrict__ out) {
    __shared__ float sc[Gq];
    __shared__ float red[256];
    int tid = threadIdx.x;
    float bb = b2[0];
    for (int gi = tid; gi < Gq; gi += 256) {
        const float* pp = g_part + (size_t)gi * 24;
        float a = 0.f;
#pragma unroll
        for (int c = 0; c < 24; c++) a += pp[c];
        sc[gi] = 1.f / (1.f + expf(-(a + bb)));
    }
    __syncthreads();
    float s = 0.f;
    for (int idx = tid; idx < Bq * NEGq; idx += 256) {
        int b = idx / NEGq;
        int j = idx % NEGq + 1;
        float v = sc[b * 16 + j] + 0.1f - sc[b * 16];
        s += fmaxf(v, 0.f);
    }
    red[tid] = s;
    __syncthreads();
    for (int o = 128; o > 0; o >>= 1) {
        if (tid < o) red[tid] += red[tid + o];
        __syncthreads();
    }
    if (tid == 0) out[0] = red[0];
}

// ---------------------------------------------------------------------------
extern "C" void kernel_launch(void* const* d_in, const int* in_sizes, int n_in,
                              void* d_out, int out_size) {
    const float* x    = (const float*)d_in[0];   // triple_emb [N, 768]
    const float* Wsfa = (const float*)d_in[1];   // [768, 768]
    const float* W1   = (const float*)d_in[2];   // [3072, 768]
    const float* b1   = (const float*)d_in[3];   // [3072]
    const float* W2   = (const float*)d_in[4];   // [1, 3072]
    const float* b2   = (const float*)d_in[5];   // [1]
    const int* sizes  = (const int*)d_in[6];     // [128, 16] -> 2048 flat
    float* out = (float*)d_out;
    int N = in_sizes[0] / Dq;

    k0_offsets<<<1, 256>>>(sizes);

    dim3 g1(Dq / 128, (N + 127) / 128);
    k1_xw_gemm<<<g1, 256>>>(x, Wsfa, N);

    const int k2_smem = (32 * XS_STR + 768 * 33 + 32 * 33 + 32) * 4;  // 204544 B
    cudaFuncSetAttribute(k2_attention, cudaFuncAttributeMaxDynamicSharedMemorySize, k2_smem);
    k2_attention<<<Gq, 256, k2_smem>>>(x, sizes);

    dim3 g3(3072 / 128, Gq / 128);
    k3_mlp<<<g3, 256>>>(W1, b1, W2);

    k4_loss<<<1, 256>>>(b2, out);
}

// round 3
// speedup vs baseline: 1.2620x; 1.2620x over previous
#include <cuda_runtime.h>
#include <math.h>

#define Dq   768
#define Gq   2048
#define Bq   128
#define NEGq 15

// Static scratch (allocation-free rule).
__device__ float g_xw[(size_t)36864 * Dq];     // xw = x @ W_sfa^T  (N rows used)
__device__ float g_pooled[(size_t)Gq * Dq];    // pooled [G, D]
__device__ float g_part[(size_t)Gq * 24];      // per (group, n-block) MLP partials
__device__ int   g_off[Gq];                    // exclusive prefix of group sizes

// ---------------------------------------------------------------------------
// packed f32x2 helpers
// ---------------------------------------------------------------------------
__device__ __forceinline__ unsigned long long bcast2(float a) {
    unsigned long long r;
    asm("mov.b64 %0, {%1, %1};" : "=l"(r) : "f"(a));
    return r;
}
__device__ __forceinline__ unsigned long long pack2(float lo, float hi) {
    unsigned long long r;
    asm("mov.b64 %0, {%1, %2};" : "=l"(r) : "f"(lo), "f"(hi));
    return r;
}
__device__ __forceinline__ void fma2(unsigned long long& d,
                                     unsigned long long a, unsigned long long b) {
    asm("fma.rn.f32x2 %0, %1, %2, %0;" : "+l"(d) : "l"(a), "l"(b));
}
__device__ __forceinline__ float2 upk(unsigned long long v) {
    float2 f;
    asm("mov.b64 {%0, %1}, %2;" : "=f"(f.x), "=f"(f.y) : "l"(v));
    return f;
}

// ---------------------------------------------------------------------------
// K0: offsets (prefix sum of 2048 sizes)
// ---------------------------------------------------------------------------
__global__ void k0_offsets(const int* __restrict__ sizes) {
    __shared__ int part[256];
    __shared__ int base[256];
    int tid = threadIdx.x;
    int loc[8];
    int ssum = 0;
#pragma unroll
    for (int i = 0; i < 8; i++) { loc[i] = ssum; ssum += sizes[tid * 8 + i]; }
    part[tid] = ssum;
    __syncthreads();
    if (tid == 0) {
        int run = 0;
        for (int i = 0; i < 256; i++) { int v = part[i]; base[i] = run; run += v; }
    }
    __syncthreads();
    int b0 = base[tid];
#pragma unroll
    for (int i = 0; i < 8; i++) g_off[tid * 8 + i] = b0 + loc[i];
}

// ---------------------------------------------------------------------------
// Shared 128x128x8 fp32 GEMM mainloop, packed f32x2 accumulators,
// double-buffered SMEM (one __syncthreads per k-step).
// acc2[i][jp] = {C[i][2jp], C[i][2jp+1]} in the (tx*4 | 64+tx*4) column layout.
// ---------------------------------------------------------------------------
__device__ __forceinline__ void gemm_tile_128x128_f32x2(
    const float* __restrict__ A, const float* __restrict__ Bm,
    int M, int K, int bm, int bn, int tid,
    float (*As)[8][128], float (*Bs)[8][128], unsigned long long acc2[8][4])
{
    int lr = tid >> 1;
    int lc = (tid & 1) << 2;
    int ar = bm + lr; if (ar >= M) ar = M - 1;   // clamp (M multiple of 128 in practice)
    const float* Ap = A  + (size_t)ar * K + lc;
    const float* Bp = Bm + (size_t)(bn + lr) * K + lc;
    int ty = tid >> 4, tx = tid & 15;

    // prologue: tile 0 -> buffer 0
    float4 av = *(const float4*)(Ap);
    float4 bv = *(const float4*)(Bp);
    As[0][lc + 0][lr] = av.x; As[0][lc + 1][lr] = av.y;
    As[0][lc + 2][lr] = av.z; As[0][lc + 3][lr] = av.w;
    Bs[0][lc + 0][lr] = bv.x; Bs[0][lc + 1][lr] = bv.y;
    Bs[0][lc + 2][lr] = bv.z; Bs[0][lc + 3][lr] = bv.w;
    __syncthreads();

    int buf = 0;
    for (int k0 = 8; k0 <= K; k0 += 8) {
        float4 av2, bv2;
        bool more = (k0 < K);
        if (more) {
            av2 = *(const float4*)(Ap + k0);
            bv2 = *(const float4*)(Bp + k0);
        }
#pragma unroll
        for (int k = 0; k < 8; k++) {
            float4 a0 = *(const float4*)&As[buf][k][ty * 4];
            float4 a1 = *(const float4*)&As[buf][k][64 + ty * 4];
            float4 b0 = *(const float4*)&Bs[buf][k][tx * 4];
            float4 b1 = *(const float4*)&Bs[buf][k][64 + tx * 4];
            unsigned long long ap[8] = {
                bcast2(a0.x), bcast2(a0.y), bcast2(a0.z), bcast2(a0.w),
                bcast2(a1.x), bcast2(a1.y), bcast2(a1.z), bcast2(a1.w)};
            unsigned long long bp[4] = {
                pack2(b0.x, b0.y), pack2(b0.z, b0.w),
                pack2(b1.x, b1.y), pack2(b1.z, b1.w)};
#pragma unroll
            for (int i = 0; i < 8; i++)
#pragma unroll
                for (int j = 0; j < 4; j++)
                    fma2(acc2[i][j], ap[i], bp[j]);
        }
        if (more) {
            int nb = buf ^ 1;
            As[nb][lc + 0][lr] = av2.x; As[nb][lc + 1][lr] = av2.y;
            As[nb][lc + 2][lr] = av2.z; As[nb][lc + 3][lr] = av2.w;
            Bs[nb][lc + 0][lr] = bv2.x; Bs[nb][lc + 1][lr] = bv2.y;
            Bs[nb][lc + 2][lr] = bv2.z; Bs[nb][lc + 3][lr] = bv2.w;
            __syncthreads();
            buf = nb;
        }
    }
}

// ---------------------------------------------------------------------------
// K1: g_xw[n,e] = sum_d x[n,d] * W_sfa[e,d]   (M=N, Nn=768, K=768)
// ---------------------------------------------------------------------------
__global__ __launch_bounds__(256) void k1_xw_gemm(
    const float* __restrict__ A, const float* __restrict__ W, int M)
{
    __shared__ float As[2][8][128];
    __shared__ float Bs[2][8][128];
    unsigned long long acc2[8][4] = {};
    int bm = blockIdx.y * 128, bn = blockIdx.x * 128;
    int tid = threadIdx.x;
    gemm_tile_128x128_f32x2(A, W, M, Dq, bm, bn, tid, As, Bs, acc2);
    int ty = tid >> 4, tx = tid & 15;
#pragma unroll
    for (int i = 0; i < 8; i++) {
        int r = bm + ((i < 4) ? (ty * 4 + i) : (64 + ty * 4 + i - 4));
        if (r < M) {
            float2 v0 = upk(acc2[i][0]), v1 = upk(acc2[i][1]);
            float2 v2 = upk(acc2[i][2]), v3 = upk(acc2[i][3]);
            *(float4*)(g_xw + (size_t)r * Dq + bn + tx * 4) =
                make_float4(v0.x, v0.y, v1.x, v1.y);
            *(float4*)(g_xw + (size_t)r * Dq + bn + 64 + tx * 4) =
                make_float4(v2.x, v2.y, v3.x, v3.y);
        }
    }
}

// ---------------------------------------------------------------------------
// K2: per-group attention + pooling. One block per group.
// xwT stride 34 (even) so the (m0, m0+1) pair is one aligned 64-bit LDS.
// ---------------------------------------------------------------------------
#define XS_STR  772   // 768 + 4 padding floats per row (float4-aligned, even)
#define XWT_STR 34    // even stride -> 8B-aligned m-pairs

__global__ __launch_bounds__(256) void k2_attention(
    const float* __restrict__ x, const int* __restrict__ sizes)
{
    extern __shared__ float sm[];
    float* xs  = sm;                          // [32][772]
    float* xwT = sm + 32 * XS_STR;            // [768][34]
    float* S   = xwT + 768 * XWT_STR;         // [32][33]
    float* att = S + 32 * 33;                 // [32]

    int g = blockIdx.x;
    int s = sizes[g];
    int base = g_off[g];
    int tid = threadIdx.x;

    const float4* xg = (const float4*)(x    + (size_t)base * Dq);
    const float4* wg = (const float4*)(g_xw + (size_t)base * Dq);
    int tot4 = s * (Dq / 4);
    for (int i = tid; i < tot4; i += 256) {
        int row = i / 192, d4 = i - row * 192;
        float4 v = xg[i];
        *(float4*)(xs + row * XS_STR + d4 * 4) = v;
        float4 w = wg[i];
        int d = d4 * 4;
        xwT[(d + 0) * XWT_STR + row] = w.x;
        xwT[(d + 1) * XWT_STR + row] = w.y;
        xwT[(d + 2) * XWT_STR + row] = w.z;
        xwT[(d + 3) * XWT_STR + row] = w.w;
    }
    __syncthreads();

    int ty = tid >> 4, tx = tid & 15;
    int l0 = ty * 2, m0 = tx * 2;
    if (l0 < s && m0 < s) {
        unsigned long long acc0 = 0ull, acc1 = 0ull;
        const float* xr0 = xs + l0 * XS_STR;
        const float* xr1 = xs + (l0 + 1) * XS_STR;  // row <= 31, in-bounds SMEM
#pragma unroll 8
        for (int d = 0; d < Dq; d++) {
            unsigned long long wp =
                *(const unsigned long long*)&xwT[d * XWT_STR + m0];
            float p0 = xr0[d];
            float p1 = xr1[d];
            fma2(acc0, bcast2(p0), wp);
            fma2(acc1, bcast2(p1), wp);
        }
        float2 r0 = upk(acc0), r1 = upk(acc1);
        S[l0 * 33 + m0] = tanhf(r0.x);
        if (m0 + 1 < s) S[l0 * 33 + m0 + 1] = tanhf(r0.y);
        if (l0 + 1 < s) {
            S[(l0 + 1) * 33 + m0] = tanhf(r1.x);
            if (m0 + 1 < s) S[(l0 + 1) * 33 + m0 + 1] = tanhf(r1.y);
        }
    }
    __syncthreads();

    // column max over l, softmax over m (warp 0)
    if (tid < 32) {
        int m = tid;
        float mx = -INFINITY;
        if (m < s)
            for (int l = 0; l < s; l++) mx = fmaxf(mx, S[l * 33 + m]);
        float wm = mx;
#pragma unroll
        for (int o = 16; o > 0; o >>= 1) wm = fmaxf(wm, __shfl_xor_sync(0xffffffffu, wm, o));
        float e = (m < s) ? expf(mx - wm) : 0.f;
        float se = e;
#pragma unroll
        for (int o = 16; o > 0; o >>= 1) se += __shfl_xor_sync(0xffffffffu, se, o);
        att[m] = e / se;
    }
    __syncthreads();

    // pooled[d] = sum_m att[m] * x[m,d]
    float* outp = g_pooled + (size_t)g * Dq;
    for (int d = tid; d < Dq; d += 256) {
        float a = 0.f;
        for (int m = 0; m < s; m++) a = fmaf(att[m], xs[m * XS_STR + d], a);
        outp[d] = a;
    }
}

// ---------------------------------------------------------------------------
// K3: fused MLP GEMM. relu(pooled@W1^T + b1) . W2 per (row, n-block) partials.
// M=2048, Nn=3072, K=768, grid (24, 16).
// ---------------------------------------------------------------------------
__global__ __launch_bounds__(256) void k3_mlp(
    const float* __restrict__ W1, const float* __restrict__ b1v,
    const float* __restrict__ W2)
{
    __shared__ float As[2][8][128];
    __shared__ float Bs[2][8][128];
    unsigned long long acc2[8][4] = {};
    int bm = blockIdx.y * 128, bn = blockIdx.x * 128;
    int tid = threadIdx.x;
    gemm_tile_128x128_f32x2(g_pooled, W1, Gq, Dq, bm, bn, tid, As, Bs, acc2);

    int ty = tid >> 4, tx = tid & 15;
    int c0 = bn + tx * 4, c1 = bn + 64 + tx * 4;
    float bb[8], ww[8];
#pragma unroll
    for (int j = 0; j < 4; j++) {
        bb[j]     = b1v[c0 + j]; ww[j]     = W2[c0 + j];
        bb[4 + j] = b1v[c1 + j]; ww[4 + j] = W2[c1 + j];
    }
    float part[8];
#pragma unroll
    for (int i = 0; i < 8; i++) {
        float av[8];
        float2 v0 = upk(acc2[i][0]), v1 = upk(acc2[i][1]);
        float2 v2 = upk(acc2[i][2]), v3 = upk(acc2[i][3]);
        av[0] = v0.x; av[1] = v0.y; av[2] = v1.x; av[3] = v1.y;
        av[4] = v2.x; av[5] = v2.y; av[6] = v3.x; av[7] = v3.y;
        float p = 0.f;
#pragma unroll
        for (int j = 0; j < 8; j++) {
            float h = av[j] + bb[j];
            p = fmaf(fmaxf(h, 0.f), ww[j], p);
        }
        part[i] = p;
    }
#pragma unroll
    for (int off = 8; off > 0; off >>= 1)
#pragma unroll
        for (int i = 0; i < 8; i++)
            part[i] += __shfl_down_sync(0xffffffffu, part[i], off, 16);
    if (tx == 0) {
#pragma unroll
        for (int i = 0; i < 8; i++) {
            int r = bm + ((i < 4) ? (ty * 4 + i) : (64 + ty * 4 + i - 4));
            g_part[(size_t)r * 24 + blockIdx.x] = part[i];
        }
    }
}

// ---------------------------------------------------------------------------
// K4: scores = sigmoid(sum(parts) + b2); margin-ranking loss reduction.
// ---------------------------------------------------------------------------
__global__ void k4_loss(const float* __restrict__ b2, float* __restrict__ out) {
    __shared__ float sc[Gq];
    __shared__ float red[256];
    int tid = threadIdx.x;
    float bb = b2[0];
    for (int gi = tid; gi < Gq; gi += 256) {
        const float* pp = g_part + (size_t)gi * 24;
        float a = 0.f;
#pragma unroll
        for (int c = 0; c < 24; c++) a += pp[c];
        sc[gi] = 1.f / (1.f + expf(-(a + bb)));
    }
    __syncthreads();
    float s = 0.f;
    for (int idx = tid; idx < Bq * NEGq; idx += 256) {
        int b = idx / NEGq;
        int j = idx % NEGq + 1;
        float v = sc[b * 16 + j] + 0.1f - sc[b * 16];
        s += fmaxf(v, 0.f);
    }
    red[tid] = s;
    __syncthreads();
    for (int o = 128; o > 0; o >>= 1) {
        if (tid < o) red[tid] += red[tid + o];
        __syncthreads();
    }
    if (tid == 0) out[0] = red[0];
}

// ---------------------------------------------------------------------------
extern "C" void kernel_launch(void* const* d_in, const int* in_sizes, int n_in,
                              void* d_out, int out_size) {
    const float* x    = (const float*)d_in[0];   // triple_emb [N, 768]
    const float* Wsfa = (const float*)d_in[1];   // [768, 768]
    const float* W1   = (const float*)d_in[2];   // [3072, 768]
    const float* b1   = (const float*)d_in[3];   // [3072]
    const float* W2   = (const float*)d_in[4];   // [1, 3072]
    const float* b2   = (const float*)d_in[5];   // [1]
    const int* sizes  = (const int*)d_in[6];     // [128, 16] -> 2048 flat
    float* out = (float*)d_out;
    int N = in_sizes[0] / Dq;

    k0_offsets<<<1, 256>>>(sizes);

    dim3 g1(Dq / 128, (N + 127) / 128);
    k1_xw_gemm<<<g1, 256>>>(x, Wsfa, N);

    const int k2_smem = (32 * XS_STR + 768 * XWT_STR + 32 * 33 + 32) * 4;  // ~207.6 KB
    cudaFuncSetAttribute(k2_attention, cudaFuncAttributeMaxDynamicSharedMemorySize, k2_smem);
    k2_attention<<<Gq, 256, k2_smem>>>(x, sizes);

    dim3 g3(3072 / 128, Gq / 128);
    k3_mlp<<<g3, 256>>>(W1, b1, W2);

    k4_loss<<<1, 256>>>(b2, out);
}

// round 7
// speedup vs baseline: 1.5907x; 1.2605x over previous
#include <cuda_runtime.h>
#include <cuda_bf16.h>
#include <math.h>

#define Dq   768
#define Gq   2048
#define Bq   128
#define NEGq 15
#define KC   64
#define NCHUNK 12
#define MAXROWS 36864

// Static scratch (allocation-free rule). NEVER passed as kernel args from
// host — device code references these symbols directly (host-side use of a
// __device__ symbol yields the host shadow address: that was the R6 bug).
__device__ float g_xw[(size_t)MAXROWS * Dq];
__device__ float g_pooled[(size_t)Gq * Dq];
__device__ float g_part[(size_t)Gq * 96];
__device__ int   g_off[Gq];

__device__ __nv_bfloat16 g_xh[(size_t)MAXROWS * Dq];
__device__ __nv_bfloat16 g_xl[(size_t)MAXROWS * Dq];
__device__ __nv_bfloat16 g_wh[(size_t)Dq * Dq];
__device__ __nv_bfloat16 g_wl[(size_t)Dq * Dq];
__device__ __nv_bfloat16 g_w1h[(size_t)3072 * Dq];
__device__ __nv_bfloat16 g_w1l[(size_t)3072 * Dq];
__device__ __nv_bfloat16 g_ph[(size_t)Gq * Dq];
__device__ __nv_bfloat16 g_pl[(size_t)Gq * Dq];

// ---------------------------------------------------------------------------
// helpers (baseline sm_80 PTX only — harness compiles for plain sm_103)
// ---------------------------------------------------------------------------
__device__ __forceinline__ unsigned smem_u32(const void* p) {
    unsigned a;
    asm("{ .reg .u64 t; cvta.to.shared.u64 t, %1; cvt.u32.u64 %0, t; }"
        : "=r"(a) : "l"(p));
    return a;
}
__device__ __forceinline__ void cpa16(unsigned d, const void* s) {
    asm volatile("cp.async.cg.shared.global [%0], [%1], 16;" :: "r"(d), "l"(s));
}
__device__ __forceinline__ void ldm4(unsigned* r, unsigned a) {
    asm volatile("ldmatrix.sync.aligned.m8n8.x4.shared.b16 {%0,%1,%2,%3}, [%4];"
                 : "=r"(r[0]), "=r"(r[1]), "=r"(r[2]), "=r"(r[3]) : "r"(a));
}
__device__ __forceinline__ void mma16816(float* d, const unsigned* a,
                                         unsigned b0, unsigned b1) {
    asm volatile("mma.sync.aligned.m16n8k16.row.col.f32.bf16.bf16.f32 "
                 "{%0,%1,%2,%3}, {%4,%5,%6,%7}, {%8,%9}, {%0,%1,%2,%3};"
                 : "+f"(d[0]), "+f"(d[1]), "+f"(d[2]), "+f"(d[3])
                 : "r"(a[0]), "r"(a[1]), "r"(a[2]), "r"(a[3]), "r"(b0), "r"(b1));
}

// ---------------------------------------------------------------------------
// fp32 -> (bf16 hi, bf16 lo residual). DST selected inside device code.
//   DST: 0 = (g_xh, g_xl)  from src
//        1 = (g_wh, g_wl)  from src
//        2 = (g_w1h, g_w1l) from src
//        3 = (g_ph, g_pl)  from g_pooled (src ignored)
// ---------------------------------------------------------------------------
template <int DST>
__global__ void kconv(const float* __restrict__ src, int n4)
{
    int i = blockIdx.x * blockDim.x + threadIdx.x;
    if (i >= n4) return;
    const float* sp = (DST == 3) ? g_pooled : src;
    __nv_bfloat16* hi = (DST == 0) ? g_xh : (DST == 1) ? g_wh : (DST == 2) ? g_w1h : g_ph;
    __nv_bfloat16* lo = (DST == 0) ? g_xl : (DST == 1) ? g_wl : (DST == 2) ? g_w1l : g_pl;
    float4 v = ((const float4*)sp)[i];
    float a[4] = {v.x, v.y, v.z, v.w};
    unsigned h[4], l[4];
#pragma unroll
    for (int j = 0; j < 4; j++) {
        __nv_bfloat16 hb = __float2bfloat16(a[j]);
        h[j] = (unsigned)__bfloat16_as_ushort(hb);
        float r = a[j] - __bfloat162float(hb);
        l[j] = (unsigned)__bfloat16_as_ushort(__float2bfloat16(r));
    }
    ((uint2*)hi)[i] = make_uint2(h[0] | (h[1] << 16), h[2] | (h[3] << 16));
    ((uint2*)lo)[i] = make_uint2(l[0] | (l[1] << 16), l[2] | (l[3] << 16));
}

// ---------------------------------------------------------------------------
// GEMM via mma.sync bf16, 3-product split precision.
// C[M,Nn] = A[M,768] @ B[Nn,768]^T ; CTA tile 128x128, K-chunk 64,
// cp.async double-buffered SMEM, pitch 144B (conflict-free ldmatrix).
// FUSE=0: A=(g_xh,g_xl), B=(g_wh,g_wl), store fp32 C into g_xw.
// FUSE=1: A=(g_ph,g_pl), B=(g_w1h,g_w1l), fused relu(D+b1).W2 -> g_part.
// ---------------------------------------------------------------------------
#define SPITCHB 144
#define TILEB   (128 * SPITCHB)   // 18432 B per matrix tile
#define BUFB    (4 * TILEB)       // Ah, Al, Bh, Bl
#define GSMEM   (2 * BUFB)        // 147456 B

template <int FUSE>
__global__ __launch_bounds__(256) void gemm_mma(
    int M, const float* __restrict__ b1v, const float* __restrict__ w2v)
{
    const __nv_bfloat16* __restrict__ Ah = FUSE ? g_ph  : g_xh;
    const __nv_bfloat16* __restrict__ Al = FUSE ? g_pl  : g_xl;
    const __nv_bfloat16* __restrict__ Bh = FUSE ? g_w1h : g_wh;
    const __nv_bfloat16* __restrict__ Bl = FUSE ? g_w1l : g_wl;

    extern __shared__ char smem[];
    unsigned sbase = smem_u32(smem);
    int tid = threadIdx.x, lane = tid & 31, wid = tid >> 5;
    int bm = blockIdx.y * 128, bn = blockIdx.x * 128;

    // staging: thread -> (row, 64B half-row); 16 cp.asyncs per chunk
    int sr = tid >> 1, sh = tid & 1;
    int arow = bm + sr; if (arow >= M) arow = M - 1;
    const __nv_bfloat16* Asrc_h = Ah + (size_t)arow * Dq + sh * 32;
    const __nv_bfloat16* Asrc_l = Al + (size_t)arow * Dq + sh * 32;
    const __nv_bfloat16* Bsrc_h = Bh + (size_t)(bn + sr) * Dq + sh * 32;
    const __nv_bfloat16* Bsrc_l = Bl + (size_t)(bn + sr) * Dq + sh * 32;
    unsigned sdst = sbase + sr * SPITCHB + sh * 64;

    float acc[4][4][4];
#pragma unroll
    for (int i = 0; i < 4; i++)
#pragma unroll
        for (int j = 0; j < 4; j++)
#pragma unroll
            for (int k = 0; k < 4; k++) acc[i][j][k] = 0.f;

    // warp tile: 64x32 at (wm, wn)
    int wm = (wid >> 2) * 64;
    int wn = (wid & 3) * 32;
    unsigned a_base = sbase + (unsigned)(wm + (lane & 15)) * SPITCHB
                            + ((lane >> 4) << 4);
    unsigned b_base = sbase + 2 * TILEB
        + (unsigned)(wn + (lane & 7) + ((lane >> 4) << 3)) * SPITCHB
        + (((lane >> 3) & 1) << 4);

    auto stage = [&](int c, int buf) {
        unsigned d = sdst + buf * BUFB;
        size_t off = (size_t)c * KC;
#pragma unroll
        for (int i = 0; i < 4; i++) {
            cpa16(d + i * 16,             Asrc_h + off + i * 8);
            cpa16(d + TILEB + i * 16,     Asrc_l + off + i * 8);
            cpa16(d + 2 * TILEB + i * 16, Bsrc_h + off + i * 8);
            cpa16(d + 3 * TILEB + i * 16, Bsrc_l + off + i * 8);
        }
        asm volatile("cp.async.commit_group;" ::: "memory");
    };

    stage(0, 0);
    asm volatile("cp.async.wait_group 0;" ::: "memory");
    __syncthreads();

    for (int c = 0; c < NCHUNK; c++) {
        if (c + 1 < NCHUNK) stage(c + 1, (c + 1) & 1);
        unsigned ab = a_base + (c & 1) * BUFB;
        unsigned bb = b_base + (c & 1) * BUFB;
#pragma unroll
        for (int ks = 0; ks < 4; ks++) {
            unsigned ahf[4][4], alf[4][4], bhf[2][4], blf[2][4];
#pragma unroll
            for (int mt = 0; mt < 4; mt++) {
                ldm4(ahf[mt], ab + mt * (16 * SPITCHB) + ks * 32);
                ldm4(alf[mt], ab + TILEB + mt * (16 * SPITCHB) + ks * 32);
            }
#pragma unroll
            for (int np = 0; np < 2; np++) {
                ldm4(bhf[np], bb + np * (16 * SPITCHB) + ks * 32);
                ldm4(blf[np], bb + TILEB + np * (16 * SPITCHB) + ks * 32);
            }
#pragma unroll
            for (int mt = 0; mt < 4; mt++)
#pragma unroll
                for (int nt = 0; nt < 4; nt++) {
                    unsigned h0 = bhf[nt >> 1][(nt & 1) * 2];
                    unsigned h1 = bhf[nt >> 1][(nt & 1) * 2 + 1];
                    unsigned l0 = blf[nt >> 1][(nt & 1) * 2];
                    unsigned l1 = blf[nt >> 1][(nt & 1) * 2 + 1];
                    mma16816(acc[mt][nt], ahf[mt], h0, h1);
                    mma16816(acc[mt][nt], ahf[mt], l0, l1);
                    mma16816(acc[mt][nt], alf[mt], h0, h1);
                }
        }
        if (c + 1 < NCHUNK) {
            asm volatile("cp.async.wait_group 0;" ::: "memory");
            __syncthreads();
        }
    }

    if (!FUSE) {
#pragma unroll
        for (int mt = 0; mt < 4; mt++) {
            int r0 = bm + wm + mt * 16 + (lane >> 2);
#pragma unroll
            for (int nt = 0; nt < 4; nt++) {
                int col = bn + wn + nt * 8 + (lane & 3) * 2;
                if (r0 < M)
                    *(float2*)(g_xw + (size_t)r0 * Dq + col) =
                        make_float2(acc[mt][nt][0], acc[mt][nt][1]);
                if (r0 + 8 < M)
                    *(float2*)(g_xw + (size_t)(r0 + 8) * Dq + col) =
                        make_float2(acc[mt][nt][2], acc[mt][nt][3]);
            }
        }
    } else {
#pragma unroll
        for (int mt = 0; mt < 4; mt++) {
            float p0 = 0.f, p1 = 0.f;
#pragma unroll
            for (int nt = 0; nt < 4; nt++) {
                int col = bn + wn + nt * 8 + (lane & 3) * 2;
                float bb0 = b1v[col], bb1 = b1v[col + 1];
                float w0 = w2v[col],  w1 = w2v[col + 1];
                p0 = fmaf(fmaxf(acc[mt][nt][0] + bb0, 0.f), w0, p0);
                p0 = fmaf(fmaxf(acc[mt][nt][1] + bb1, 0.f), w1, p0);
                p1 = fmaf(fmaxf(acc[mt][nt][2] + bb0, 0.f), w0, p1);
                p1 = fmaf(fmaxf(acc[mt][nt][3] + bb1, 0.f), w1, p1);
            }
            p0 += __shfl_xor_sync(0xffffffffu, p0, 1);
            p0 += __shfl_xor_sync(0xffffffffu, p0, 2);
            p1 += __shfl_xor_sync(0xffffffffu, p1, 1);
            p1 += __shfl_xor_sync(0xffffffffu, p1, 2);
            if ((lane & 3) == 0) {
                int r0 = bm + wm + mt * 16 + (lane >> 2);
                int pc = blockIdx.x * 4 + (wid & 3);
                g_part[(size_t)r0 * 96 + pc] = p0;
                g_part[(size_t)(r0 + 8) * 96 + pc] = p1;
            }
        }
    }
}

// ---------------------------------------------------------------------------
// K0: offsets (prefix sum of 2048 sizes)
// ---------------------------------------------------------------------------
__global__ void k0_offsets(const int* __restrict__ sizes) {
    __shared__ int part[256];
    __shared__ int base[256];
    int tid = threadIdx.x;
    int loc[8];
    int ssum = 0;
#pragma unroll
    for (int i = 0; i < 8; i++) { loc[i] = ssum; ssum += sizes[tid * 8 + i]; }
    part[tid] = ssum;
    __syncthreads();
    if (tid == 0) {
        int run = 0;
        for (int i = 0; i < 256; i++) { int v = part[i]; base[i] = run; run += v; }
    }
    __syncthreads();
    int b0 = base[tid];
#pragma unroll
    for (int i = 0; i < 8; i++) g_off[tid * 8 + i] = b0 + loc[i];
}

// ---------------------------------------------------------------------------
// packed f32x2 helpers (K2)
// ---------------------------------------------------------------------------
__device__ __forceinline__ unsigned long long bcast2(float a) {
    unsigned long long r;
    asm("mov.b64 %0, {%1, %1};" : "=l"(r) : "f"(a));
    return r;
}
__device__ __forceinline__ void fma2(unsigned long long& d,
                                     unsigned long long a, unsigned long long b) {
    asm("fma.rn.f32x2 %0, %1, %2, %0;" : "+l"(d) : "l"(a), "l"(b));
}
__device__ __forceinline__ float2 upk(unsigned long long v) {
    float2 f;
    asm("mov.b64 {%0, %1}, %2;" : "=f"(f.x), "=f"(f.y) : "l"(v));
    return f;
}

// ---------------------------------------------------------------------------
// K2: per-group attention + pooling (passing since R3)
// ---------------------------------------------------------------------------
#define XS_STR  772
#define XWT_STR 34

__global__ __launch_bounds__(256) void k2_attention(
    const float* __restrict__ x, const int* __restrict__ sizes)
{
    extern __shared__ float sm[];
    float* xs  = sm;
    float* xwT = sm + 32 * XS_STR;
    float* S   = xwT + 768 * XWT_STR;
    float* att = S + 32 * 33;

    int g = blockIdx.x;
    int s = sizes[g];
    int base = g_off[g];
    int tid = threadIdx.x;

    const float4* xg = (const float4*)(x    + (size_t)base * Dq);
    const float4* wg = (const float4*)(g_xw + (size_t)base * Dq);
    int tot4 = s * (Dq / 4);
    for (int i = tid; i < tot4; i += 256) {
        int row = i / 192, d4 = i - row * 192;
        float4 v = xg[i];
        *(float4*)(xs + row * XS_STR + d4 * 4) = v;
        float4 w = wg[i];
        int d = d4 * 4;
        xwT[(d + 0) * XWT_STR + row] = w.x;
        xwT[(d + 1) * XWT_STR + row] = w.y;
        xwT[(d + 2) * XWT_STR + row] = w.z;
        xwT[(d + 3) * XWT_STR + row] = w.w;
    }
    __syncthreads();

    int ty = tid >> 4, tx = tid & 15;
    int l0 = ty * 2, m0 = tx * 2;
    if (l0 < s && m0 < s) {
        unsigned long long acc0 = 0ull, acc1 = 0ull;
        const float* xr0 = xs + l0 * XS_STR;
        const float* xr1 = xs + (l0 + 1) * XS_STR;
#pragma unroll 8
        for (int d = 0; d < Dq; d++) {
            unsigned long long wp =
                *(const unsigned long long*)&xwT[d * XWT_STR + m0];
            fma2(acc0, bcast2(xr0[d]), wp);
            fma2(acc1, bcast2(xr1[d]), wp);
        }
        float2 r0 = upk(acc0), r1 = upk(acc1);
        S[l0 * 33 + m0] = tanhf(r0.x);
        if (m0 + 1 < s) S[l0 * 33 + m0 + 1] = tanhf(r0.y);
        if (l0 + 1 < s) {
            S[(l0 + 1) * 33 + m0] = tanhf(r1.x);
            if (m0 + 1 < s) S[(l0 + 1) * 33 + m0 + 1] = tanhf(r1.y);
        }
    }
    __syncthreads();

    if (tid < 32) {
        int m = tid;
        float mx = -INFINITY;
        if (m < s)
            for (int l = 0; l < s; l++) mx = fmaxf(mx, S[l * 33 + m]);
        float wm = mx;
#pragma unroll
        for (int o = 16; o > 0; o >>= 1) wm = fmaxf(wm, __shfl_xor_sync(0xffffffffu, wm, o));
        float e = (m < s) ? expf(mx - wm) : 0.f;
        float se = e;
#pragma unroll
        for (int o = 16; o > 0; o >>= 1) se += __shfl_xor_sync(0xffffffffu, se, o);
        att[m] = e / se;
    }
    __syncthreads();

    float* outp = g_pooled + (size_t)g * Dq;
    for (int d = tid; d < Dq; d += 256) {
        float a = 0.f;
        for (int m = 0; m < s; m++) a = fmaf(att[m], xs[m * XS_STR + d], a);
        outp[d] = a;
    }
}

// ---------------------------------------------------------------------------
// K4: scores = sigmoid(sum of 96 partials + b2); margin-ranking loss.
// ---------------------------------------------------------------------------
__global__ void k4_loss(const float* __restrict__ b2, float* __restrict__ out) {
    __shared__ float sc[Gq];
    __shared__ float red[256];
    int tid = threadIdx.x;
    float bb = b2[0];
    for (int gi = tid; gi < Gq; gi += 256) {
        const float* pp = g_part + (size_t)gi * 96;
        float a = 0.f;
#pragma unroll
        for (int c = 0; c < 96; c++) a += pp[c];
        sc[gi] = 1.f / (1.f + expf(-(a + bb)));
    }
    __syncthreads();
    float s = 0.f;
    for (int idx = tid; idx < Bq * NEGq; idx += 256) {
        int b = idx / NEGq;
        int j = idx % NEGq + 1;
        float v = sc[b * 16 + j] + 0.1f - sc[b * 16];
        s += fmaxf(v, 0.f);
    }
    red[tid] = s;
    __syncthreads();
    for (int o = 128; o > 0; o >>= 1) {
        if (tid < o) red[tid] += red[tid + o];
        __syncthreads();
    }
    if (tid == 0) out[0] = red[0];
}

// ---------------------------------------------------------------------------
extern "C" void kernel_launch(void* const* d_in, const int* in_sizes, int n_in,
                              void* d_out, int out_size) {
    const float* x    = (const float*)d_in[0];
    const float* Wsfa = (const float*)d_in[1];
    const float* W1   = (const float*)d_in[2];
    const float* b1   = (const float*)d_in[3];
    const float* W2   = (const float*)d_in[4];
    const float* b2   = (const float*)d_in[5];
    const int* sizes  = (const int*)d_in[6];
    float* out = (float*)d_out;
    int N = in_sizes[0] / Dq;

    cudaFuncSetAttribute(gemm_mma<0>, cudaFuncAttributeMaxDynamicSharedMemorySize, GSMEM);
    cudaFuncSetAttribute(gemm_mma<1>, cudaFuncAttributeMaxDynamicSharedMemorySize, GSMEM);
    const int k2_smem = (32 * XS_STR + 768 * XWT_STR + 32 * 33 + 32) * 4;
    cudaFuncSetAttribute(k2_attention, cudaFuncAttributeMaxDynamicSharedMemorySize, k2_smem);

    k0_offsets<<<1, 256>>>(sizes);

    int n4x = N * Dq / 4;
    kconv<0><<<(n4x + 255) / 256, 256>>>(x, n4x);
    kconv<1><<<(Dq * Dq / 4 + 255) / 256, 256>>>(Wsfa, Dq * Dq / 4);
    kconv<2><<<(3072 * Dq / 4 + 255) / 256, 256>>>(W1, 3072 * Dq / 4);

    dim3 g1(Dq / 128, (N + 127) / 128);
    gemm_mma<0><<<g1, 256, GSMEM>>>(N, nullptr, nullptr);

    k2_attention<<<Gq, 256, k2_smem>>>(x, sizes);

    kconv<3><<<(Gq * Dq / 4 + 255) / 256, 256>>>(nullptr, Gq * Dq / 4);

    dim3 g3(3072 / 128, Gq / 128);
    gemm_mma<1><<<g3, 256, GSMEM>>>(Gq, b1, W2);

    k4_loss<<<1, 256>>>(b2, out);
}

// round 9
// speedup vs baseline: 2.0619x; 1.2962x over previous
#include <cuda_runtime.h>
#include <cuda_fp16.h>
#include <math.h>

#define Dq   768
#define Gq   2048
#define Bq   128
#define NEGq 15
#define KC   64
#define NCHUNK 12
#define MAXROWS 36864

// Static scratch (allocation-free rule). Device symbols are referenced ONLY
// from device code (host use of a __device__ symbol address was the R6 bug).
__device__ float g_xw[(size_t)MAXROWS * Dq];
__device__ float g_pooled[(size_t)Gq * Dq];
__device__ float g_part[(size_t)Gq * 96];
__device__ int   g_off[Gq];

__device__ __half g_xh[(size_t)MAXROWS * Dq];     // x, single fp16 (A side)
__device__ __half g_wh[(size_t)Dq * Dq];          // Wsfa hi
__device__ __half g_wl[(size_t)Dq * Dq];          // Wsfa lo residual
__device__ __half g_w1h[(size_t)3072 * Dq];       // W1 hi
__device__ __half g_w1l[(size_t)3072 * Dq];       // W1 lo residual
__device__ __half g_ph[(size_t)Gq * Dq];          // pooled, single fp16

// ---------------------------------------------------------------------------
// helpers (baseline sm_80 PTX only — harness compiles for plain sm_103)
// ---------------------------------------------------------------------------
__device__ __forceinline__ unsigned smem_u32(const void* p) {
    unsigned a;
    asm("{ .reg .u64 t; cvta.to.shared.u64 t, %1; cvt.u32.u64 %0, t; }"
        : "=r"(a) : "l"(p));
    return a;
}
__device__ __forceinline__ void cpa16(unsigned d, const void* s) {
    asm volatile("cp.async.cg.shared.global [%0], [%1], 16;" :: "r"(d), "l"(s));
}
__device__ __forceinline__ void ldm4(unsigned* r, unsigned a) {
    asm volatile("ldmatrix.sync.aligned.m8n8.x4.shared.b16 {%0,%1,%2,%3}, [%4];"
                 : "=r"(r[0]), "=r"(r[1]), "=r"(r[2]), "=r"(r[3]) : "r"(a));
}
__device__ __forceinline__ void mma16816(float* d, const unsigned* a,
                                         unsigned b0, unsigned b1) {
    asm volatile("mma.sync.aligned.m16n8k16.row.col.f32.f16.f16.f32 "
                 "{%0,%1,%2,%3}, {%4,%5,%6,%7}, {%8,%9}, {%0,%1,%2,%3};"
                 : "+f"(d[0]), "+f"(d[1]), "+f"(d[2]), "+f"(d[3])
                 : "r"(a[0]), "r"(a[1]), "r"(a[2]), "r"(a[3]), "r"(b0), "r"(b1));
}

// ---------------------------------------------------------------------------
// conversions: fp32 -> fp16 single (A-side) or hi/lo split (B-side weights).
// Destination arrays selected inside device code via template.
// ---------------------------------------------------------------------------
template <int DST>   // 0: g_xh <- src ; 1: g_ph <- g_pooled
__global__ void kconv_single(const float* __restrict__ src, int n4)
{
    int i = blockIdx.x * blockDim.x + threadIdx.x;
    if (i >= n4) return;
    const float* sp = (DST == 1) ? g_pooled : src;
    __half* hi = (DST == 0) ? g_xh : g_ph;
    float4 v = ((const float4*)sp)[i];
    float a[4] = {v.x, v.y, v.z, v.w};
    unsigned h[4];
#pragma unroll
    for (int j = 0; j < 4; j++)
        h[j] = (unsigned)__half_as_ushort(__float2half_rn(a[j]));
    ((uint2*)hi)[i] = make_uint2(h[0] | (h[1] << 16), h[2] | (h[3] << 16));
}

template <int DST>   // 0: (g_wh, g_wl) <- src ; 1: (g_w1h, g_w1l) <- src
__global__ void kconv_split(const float* __restrict__ src, int n4)
{
    int i = blockIdx.x * blockDim.x + threadIdx.x;
    if (i >= n4) return;
    __half* hi = (DST == 0) ? g_wh : g_w1h;
    __half* lo = (DST == 0) ? g_wl : g_w1l;
    float4 v = ((const float4*)src)[i];
    float a[4] = {v.x, v.y, v.z, v.w};
    unsigned h[4], l[4];
#pragma unroll
    for (int j = 0; j < 4; j++) {
        __half hb = __float2half_rn(a[j]);
        h[j] = (unsigned)__half_as_ushort(hb);
        float r = a[j] - __half2float(hb);
        l[j] = (unsigned)__half_as_ushort(__float2half_rn(r));
    }
    ((uint2*)hi)[i] = make_uint2(h[0] | (h[1] << 16), h[2] | (h[3] << 16));
    ((uint2*)lo)[i] = make_uint2(l[0] | (l[1] << 16), l[2] | (l[3] << 16));
}

// ---------------------------------------------------------------------------
// GEMM via mma.sync fp16, 2-product split (A single, B = Bh + Bl).
// C[M,Nn] = A[M,768] @ B[Nn,768]^T ; CTA tile 128x128, K-chunk 64,
// cp.async double-buffered SMEM (3 tiles/buf), pitch 144B, 2 CTAs/SM.
// FUSE=0: A=g_xh, B=(g_wh,g_wl), store fp32 C into g_xw.
// FUSE=1: A=g_ph, B=(g_w1h,g_w1l), fused relu(D+b1).W2 -> g_part.
// ---------------------------------------------------------------------------
#define SPITCHB 144
#define TILEB   (128 * SPITCHB)   // 18432 B per matrix tile
#define BUFB    (3 * TILEB)       // A, Bh, Bl
#define GSMEM   (2 * BUFB)        // 110592 B

template <int FUSE>
__global__ __launch_bounds__(256, 2) void gemm_mma(
    int M, const float* __restrict__ b1v, const float* __restrict__ w2v)
{
    const __half* __restrict__ Aa = FUSE ? g_ph  : g_xh;
    const __half* __restrict__ Bh = FUSE ? g_w1h : g_wh;
    const __half* __restrict__ Bl = FUSE ? g_w1l : g_wl;

    extern __shared__ char smem[];
    unsigned sbase = smem_u32(smem);
    int tid = threadIdx.x, lane = tid & 31, wid = tid >> 5;
    int bm = blockIdx.y * 128, bn = blockIdx.x * 128;

    // staging: thread -> (row, 64B half-row); 12 cp.asyncs per chunk
    int sr = tid >> 1, sh = tid & 1;
    int arow = bm + sr; if (arow >= M) arow = M - 1;
    const __half* Asrc  = Aa + (size_t)arow * Dq + sh * 32;
    const __half* Bsrch = Bh + (size_t)(bn + sr) * Dq + sh * 32;
    const __half* Bsrcl = Bl + (size_t)(bn + sr) * Dq + sh * 32;
    unsigned sdst = sbase + sr * SPITCHB + sh * 64;

    float acc[4][4][4];
#pragma unroll
    for (int i = 0; i < 4; i++)
#pragma unroll
        for (int j = 0; j < 4; j++)
#pragma unroll
            for (int k = 0; k < 4; k++) acc[i][j][k] = 0.f;

    // warp tile: 64x32 at (wm, wn)
    int wm = (wid >> 2) * 64;
    int wn = (wid & 3) * 32;
    unsigned a_base = sbase + (unsigned)(wm + (lane & 15)) * SPITCHB
                            + ((lane >> 4) << 4);
    unsigned b_off  = (unsigned)(wn + (lane & 7) + ((lane >> 4) << 3)) * SPITCHB
                    + (((lane >> 3) & 1) << 4);
    unsigned bh_base = sbase + TILEB + b_off;
    unsigned bl_base = sbase + 2 * TILEB + b_off;

    auto stage = [&](int c, int buf) {
        unsigned d = sdst + buf * BUFB;
        size_t off = (size_t)c * KC;
#pragma unroll
        for (int i = 0; i < 4; i++) {
            cpa16(d + i * 16,             Asrc  + off + i * 8);
            cpa16(d + TILEB + i * 16,     Bsrch + off + i * 8);
            cpa16(d + 2 * TILEB + i * 16, Bsrcl + off + i * 8);
        }
        asm volatile("cp.async.commit_group;" ::: "memory");
    };

    stage(0, 0);
    asm volatile("cp.async.wait_group 0;" ::: "memory");
    __syncthreads();

    for (int c = 0; c < NCHUNK; c++) {
        if (c + 1 < NCHUNK) stage(c + 1, (c + 1) & 1);
        unsigned ab = a_base  + (c & 1) * BUFB;
        unsigned hb = bh_base + (c & 1) * BUFB;
        unsigned lb = bl_base + (c & 1) * BUFB;
#pragma unroll
        for (int ks = 0; ks < 4; ks++) {
            unsigned af[4][4], bhf[2][4], blf[2][4];
#pragma unroll
            for (int mt = 0; mt < 4; mt++)
                ldm4(af[mt], ab + mt * (16 * SPITCHB) + ks * 32);
#pragma unroll
            for (int np = 0; np < 2; np++) {
                ldm4(bhf[np], hb + np * (16 * SPITCHB) + ks * 32);
                ldm4(blf[np], lb + np * (16 * SPITCHB) + ks * 32);
            }
#pragma unroll
            for (int mt = 0; mt < 4; mt++)
#pragma unroll
                for (int nt = 0; nt < 4; nt++) {
                    unsigned h0 = bhf[nt >> 1][(nt & 1) * 2];
                    unsigned h1 = bhf[nt >> 1][(nt & 1) * 2 + 1];
                    unsigned l0 = blf[nt >> 1][(nt & 1) * 2];
                    unsigned l1 = blf[nt >> 1][(nt & 1) * 2 + 1];
                    mma16816(acc[mt][nt], af[mt], h0, h1);
                    mma16816(acc[mt][nt], af[mt], l0, l1);
                }
        }
        if (c + 1 < NCHUNK) {
            asm volatile("cp.async.wait_group 0;" ::: "memory");
            __syncthreads();
        }
    }

    if (!FUSE) {
#pragma unroll
        for (int mt = 0; mt < 4; mt++) {
            int r0 = bm + wm + mt * 16 + (lane >> 2);
#pragma unroll
            for (int nt = 0; nt < 4; nt++) {
                int col = bn + wn + nt * 8 + (lane & 3) * 2;
                if (r0 < M)
                    *(float2*)(g_xw + (size_t)r0 * Dq + col) =
                        make_float2(acc[mt][nt][0], acc[mt][nt][1]);
                if (r0 + 8 < M)
                    *(float2*)(g_xw + (size_t)(r0 + 8) * Dq + col) =
                        make_float2(acc[mt][nt][2], acc[mt][nt][3]);
            }
        }
    } else {
#pragma unroll
        for (int mt = 0; mt < 4; mt++) {
            float p0 = 0.f, p1 = 0.f;
#pragma unroll
            for (int nt = 0; nt < 4; nt++) {
                int col = bn + wn + nt * 8 + (lane & 3) * 2;
                float bb0 = b1v[col], bb1 = b1v[col + 1];
                float w0 = w2v[col],  w1 = w2v[col + 1];
                p0 = fmaf(fmaxf(acc[mt][nt][0] + bb0, 0.f), w0, p0);
                p0 = fmaf(fmaxf(acc[mt][nt][1] + bb1, 0.f), w1, p0);
                p1 = fmaf(fmaxf(acc[mt][nt][2] + bb0, 0.f), w0, p1);
                p1 = fmaf(fmaxf(acc[mt][nt][3] + bb1, 0.f), w1, p1);
            }
            p0 += __shfl_xor_sync(0xffffffffu, p0, 1);
            p0 += __shfl_xor_sync(0xffffffffu, p0, 2);
            p1 += __shfl_xor_sync(0xffffffffu, p1, 1);
            p1 += __shfl_xor_sync(0xffffffffu, p1, 2);
            if ((lane & 3) == 0) {
                int r0 = bm + wm + mt * 16 + (lane >> 2);
                int pc = blockIdx.x * 4 + (wid & 3);
                g_part[(size_t)r0 * 96 + pc] = p0;
                g_part[(size_t)(r0 + 8) * 96 + pc] = p1;
            }
        }
    }
}

// ---------------------------------------------------------------------------
// K0: offsets (prefix sum of 2048 sizes)
// ---------------------------------------------------------------------------
__global__ void k0_offsets(const int* __restrict__ sizes) {
    __shared__ int part[256];
    __shared__ int base[256];
    int tid = threadIdx.x;
    int loc[8];
    int ssum = 0;
#pragma unroll
    for (int i = 0; i < 8; i++) { loc[i] = ssum; ssum += sizes[tid * 8 + i]; }
    part[tid] = ssum;
    __syncthreads();
    if (tid == 0) {
        int run = 0;
        for (int i = 0; i < 256; i++) { int v = part[i]; base[i] = run; run += v; }
    }
    __syncthreads();
    int b0 = base[tid];
#pragma unroll
    for (int i = 0; i < 8; i++) g_off[tid * 8 + i] = b0 + loc[i];
}

// ---------------------------------------------------------------------------
// packed f32x2 helpers (K2)
// ---------------------------------------------------------------------------
__device__ __forceinline__ unsigned long long bcast2(float a) {
    unsigned long long r;
    asm("mov.b64 %0, {%1, %1};" : "=l"(r) : "f"(a));
    return r;
}
__device__ __forceinline__ void fma2(unsigned long long& d,
                                     unsigned long long a, unsigned long long b) {
    asm("fma.rn.f32x2 %0, %1, %2, %0;" : "+l"(d) : "l"(a), "l"(b));
}
__device__ __forceinline__ float2 upk(unsigned long long v) {
    float2 f;
    asm("mov.b64 {%0, %1}, %2;" : "=f"(f.x), "=f"(f.y) : "l"(v));
    return f;
}

// ---------------------------------------------------------------------------
// K2: per-group attention + pooling (passing since R3)
// ---------------------------------------------------------------------------
#define XS_STR  772
#define XWT_STR 34

__global__ __launch_bounds__(256) void k2_attention(
    const float* __restrict__ x, const int* __restrict__ sizes)
{
    extern __shared__ float sm[];
    float* xs  = sm;
    float* xwT = sm + 32 * XS_STR;
    float* S   = xwT + 768 * XWT_STR;
    float* att = S + 32 * 33;

    int g = blockIdx.x;
    int s = sizes[g];
    int base = g_off[g];
    int tid = threadIdx.x;

    const float4* xg = (const float4*)(x    + (size_t)base * Dq);
    const float4* wg = (const float4*)(g_xw + (size_t)base * Dq);
    int tot4 = s * (Dq / 4);
    for (int i = tid; i < tot4; i += 256) {
        int row = i / 192, d4 = i - row * 192;
        float4 v = xg[i];
        *(float4*)(xs + row * XS_STR + d4 * 4) = v;
        float4 w = wg[i];
        int d = d4 * 4;
        xwT[(d + 0) * XWT_STR + row] = w.x;
        xwT[(d + 1) * XWT_STR + row] = w.y;
        xwT[(d + 2) * XWT_STR + row] = w.z;
        xwT[(d + 3) * XWT_STR + row] = w.w;
    }
    __syncthreads();

    int ty = tid >> 4, tx = tid & 15;
    int l0 = ty * 2, m0 = tx * 2;
    if (l0 < s && m0 < s) {
        unsigned long long acc0 = 0ull, acc1 = 0ull;
        const float* xr0 = xs + l0 * XS_STR;
        const float* xr1 = xs + (l0 + 1) * XS_STR;
#pragma unroll 8
        for (int d = 0; d < Dq; d++) {
            unsigned long long wp =
                *(const unsigned long long*)&xwT[d * XWT_STR + m0];
            fma2(acc0, bcast2(xr0[d]), wp);
            fma2(acc1, bcast2(xr1[d]), wp);
        }
        float2 r0 = upk(acc0), r1 = upk(acc1);
        S[l0 * 33 + m0] = tanhf(r0.x);
        if (m0 + 1 < s) S[l0 * 33 + m0 + 1] = tanhf(r0.y);
        if (l0 + 1 < s) {
            S[(l0 + 1) * 33 + m0] = tanhf(r1.x);
            if (m0 + 1 < s) S[(l0 + 1) * 33 + m0 + 1] = tanhf(r1.y);
        }
    }
    __syncthreads();

    if (tid < 32) {
        int m = tid;
        float mx = -INFINITY;
        if (m < s)
            for (int l = 0; l < s; l++) mx = fmaxf(mx, S[l * 33 + m]);
        float wm = mx;
#pragma unroll
        for (int o = 16; o > 0; o >>= 1) wm = fmaxf(wm, __shfl_xor_sync(0xffffffffu, wm, o));
        float e = (m < s) ? expf(mx - wm) : 0.f;
        float se = e;
#pragma unroll
        for (int o = 16; o > 0; o >>= 1) se += __shfl_xor_sync(0xffffffffu, se, o);
        att[m] = e / se;
    }
    __syncthreads();

    float* outp = g_pooled + (size_t)g * Dq;
    for (int d = tid; d < Dq; d += 256) {
        float a = 0.f;
        for (int m = 0; m < s; m++) a = fmaf(att[m], xs[m * XS_STR + d], a);
        outp[d] = a;
    }
}

// ---------------------------------------------------------------------------
// K4: scores = sigmoid(sum of 96 partials + b2); margin-ranking loss.
// ---------------------------------------------------------------------------
__global__ void k4_loss(const float* __restrict__ b2, float* __restrict__ out) {
    __shared__ float sc[Gq];
    __shared__ float red[256];
    int tid = threadIdx.x;
    float bb = b2[0];
    for (int gi = tid; gi < Gq; gi += 256) {
        const float* pp = g_part + (size_t)gi * 96;
        float a = 0.f;
#pragma unroll
        for (int c = 0; c < 96; c++) a += pp[c];
        sc[gi] = 1.f / (1.f + expf(-(a + bb)));
    }
    __syncthreads();
    float s = 0.f;
    for (int idx = tid; idx < Bq * NEGq; idx += 256) {
        int b = idx / NEGq;
        int j = idx % NEGq + 1;
        float v = sc[b * 16 + j] + 0.1f - sc[b * 16];
        s += fmaxf(v, 0.f);
    }
    red[tid] = s;
    __syncthreads();
    for (int o = 128; o > 0; o >>= 1) {
        if (tid < o) red[tid] += red[tid + o];
        __syncthreads();
    }
    if (tid == 0) out[0] = red[0];
}

// ---------------------------------------------------------------------------
extern "C" void kernel_launch(void* const* d_in, const int* in_sizes, int n_in,
                              void* d_out, int out_size) {
    const float* x    = (const float*)d_in[0];
    const float* Wsfa = (const float*)d_in[1];
    const float* W1   = (const float*)d_in[2];
    const float* b1   = (const float*)d_in[3];
    const float* W2   = (const float*)d_in[4];
    const float* b2   = (const float*)d_in[5];
    const int* sizes  = (const int*)d_in[6];
    float* out = (float*)d_out;
    int N = in_sizes[0] / Dq;

    cudaFuncSetAttribute(gemm_mma<0>, cudaFuncAttributeMaxDynamicSharedMemorySize, GSMEM);
    cudaFuncSetAttribute(gemm_mma<1>, cudaFuncAttributeMaxDynamicSharedMemorySize, GSMEM);
    const int k2_smem = (32 * XS_STR + 768 * XWT_STR + 32 * 33 + 32) * 4;
    cudaFuncSetAttribute(k2_attention, cudaFuncAttributeMaxDynamicSharedMemorySize, k2_smem);

    k0_offsets<<<1, 256>>>(sizes);

    int n4x = N * Dq / 4;
    kconv_single<0><<<(n4x + 255) / 256, 256>>>(x, n4x);
    kconv_split<0><<<(Dq * Dq / 4 + 255) / 256, 256>>>(Wsfa, Dq * Dq / 4);
    kconv_split<1><<<(3072 * Dq / 4 + 255) / 256, 256>>>(W1, 3072 * Dq / 4);

    dim3 g1(Dq / 128, (N + 127) / 128);
    gemm_mma<0><<<g1, 256, GSMEM>>>(N, nullptr, nullptr);

    k2_attention<<<Gq, 256, k2_smem>>>(x, sizes);

    kconv_single<1><<<(Gq * Dq / 4 + 255) / 256, 256>>>(nullptr, Gq * Dq / 4);

    dim3 g3(3072 / 128, Gq / 128);
    gemm_mma<1><<<g3, 256, GSMEM>>>(Gq, b1, W2);

    k4_loss<<<1, 256>>>(b2, out);
}

// round 10
// speedup vs baseline: 2.5860x; 1.2542x over previous
#include <cuda_runtime.h>
#include <cuda_fp16.h>
#include <math.h>

#define Dq   768
#define Gq   2048
#define Bq   128
#define NEGq 15
#define KC   64
#define NCHUNK 12
#define MAXROWS 36864

// Static scratch (allocation-free rule). Device symbols are referenced ONLY
// from device code (host use of a __device__ symbol address was the R6 bug).
__device__ float g_xw[(size_t)MAXROWS * Dq];
__device__ float g_pooled[(size_t)Gq * Dq];
__device__ float g_part[(size_t)Gq * 96];
__device__ int   g_off[Gq];

__device__ __half g_xh[(size_t)MAXROWS * Dq];     // x fp16
__device__ __half g_wh[(size_t)Dq * Dq];          // Wsfa fp16
__device__ __half g_w1h[(size_t)3072 * Dq];       // W1 fp16
__device__ __half g_ph[(size_t)Gq * Dq];          // pooled fp16

// ---------------------------------------------------------------------------
// helpers (baseline sm_80 PTX only — harness compiles for plain sm_103)
// ---------------------------------------------------------------------------
__device__ __forceinline__ unsigned smem_u32(const void* p) {
    unsigned a;
    asm("{ .reg .u64 t; cvta.to.shared.u64 t, %1; cvt.u32.u64 %0, t; }"
        : "=r"(a) : "l"(p));
    return a;
}
__device__ __forceinline__ void cpa16(unsigned d, const void* s) {
    asm volatile("cp.async.cg.shared.global [%0], [%1], 16;" :: "r"(d), "l"(s));
}
__device__ __forceinline__ void ldm4(unsigned* r, unsigned a) {
    asm volatile("ldmatrix.sync.aligned.m8n8.x4.shared.b16 {%0,%1,%2,%3}, [%4];"
                 : "=r"(r[0]), "=r"(r[1]), "=r"(r[2]), "=r"(r[3]) : "r"(a));
}
__device__ __forceinline__ void mma16816(float* d, const unsigned* a,
                                         unsigned b0, unsigned b1) {
    asm volatile("mma.sync.aligned.m16n8k16.row.col.f32.f16.f16.f32 "
                 "{%0,%1,%2,%3}, {%4,%5,%6,%7}, {%8,%9}, {%0,%1,%2,%3};"
                 : "+f"(d[0]), "+f"(d[1]), "+f"(d[2]), "+f"(d[3])
                 : "r"(a[0]), "r"(a[1]), "r"(a[2]), "r"(a[3]), "r"(b0), "r"(b1));
}

// ---------------------------------------------------------------------------
// fp32 -> fp16 conversion. Destination selected inside device code.
//   DST 0: g_xh <- src ; 1: g_ph <- g_pooled ; 2: g_wh <- src ; 3: g_w1h <- src
// ---------------------------------------------------------------------------
template <int DST>
__global__ void kconv(const float* __restrict__ src, int n4)
{
    int i = blockIdx.x * blockDim.x + threadIdx.x;
    if (i >= n4) return;
    const float* sp = (DST == 1) ? g_pooled : src;
    __half* hi = (DST == 0) ? g_xh : (DST == 1) ? g_ph : (DST == 2) ? g_wh : g_w1h;
    float4 v = ((const float4*)sp)[i];
    float a[4] = {v.x, v.y, v.z, v.w};
    unsigned h[4];
#pragma unroll
    for (int j = 0; j < 4; j++)
        h[j] = (unsigned)__half_as_ushort(__float2half_rn(a[j]));
    ((uint2*)hi)[i] = make_uint2(h[0] | (h[1] << 16), h[2] | (h[3] << 16));
}

// ---------------------------------------------------------------------------
// GEMM via mma.sync fp16 (pure single-product).
// C[M,Nn] = A[M,768] @ B[Nn,768]^T ; CTA tile 128x128, K-chunk 64,
// cp.async double-buffered SMEM (2 tiles/buf), pitch 144B, 2 CTAs/SM.
// FUSE=0: A=g_xh, B=g_wh, store fp32 C into g_xw.
// FUSE=1: A=g_ph, B=g_w1h, fused relu(D+b1).W2 -> g_part.
// ---------------------------------------------------------------------------
#define SPITCHB 144
#define TILEB   (128 * SPITCHB)   // 18432 B per matrix tile
#define BUFB    (2 * TILEB)       // A, B
#define GSMEM   (2 * BUFB)        // 73728 B

template <int FUSE>
__global__ __launch_bounds__(256, 2) void gemm_mma(
    int M, const float* __restrict__ b1v, const float* __restrict__ w2v)
{
    const __half* __restrict__ Aa = FUSE ? g_ph  : g_xh;
    const __half* __restrict__ Bh = FUSE ? g_w1h : g_wh;

    extern __shared__ char smem[];
    unsigned sbase = smem_u32(smem);
    int tid = threadIdx.x, lane = tid & 31, wid = tid >> 5;
    int bm = blockIdx.y * 128, bn = blockIdx.x * 128;

    // staging: thread -> (row, 64B half-row); 8 cp.asyncs per chunk
    int sr = tid >> 1, sh = tid & 1;
    int arow = bm + sr; if (arow >= M) arow = M - 1;
    const __half* Asrc  = Aa + (size_t)arow * Dq + sh * 32;
    const __half* Bsrch = Bh + (size_t)(bn + sr) * Dq + sh * 32;
    unsigned sdst = sbase + sr * SPITCHB + sh * 64;

    float acc[4][4][4];
#pragma unroll
    for (int i = 0; i < 4; i++)
#pragma unroll
        for (int j = 0; j < 4; j++)
#pragma unroll
            for (int k = 0; k < 4; k++) acc[i][j][k] = 0.f;

    // warp tile: 64x32 at (wm, wn)
    int wm = (wid >> 2) * 64;
    int wn = (wid & 3) * 32;
    unsigned a_base = sbase + (unsigned)(wm + (lane & 15)) * SPITCHB
                            + ((lane >> 4) << 4);
    unsigned bh_base = sbase + TILEB
        + (unsigned)(wn + (lane & 7) + ((lane >> 4) << 3)) * SPITCHB
        + (((lane >> 3) & 1) << 4);

    auto stage = [&](int c, int buf) {
        unsigned d = sdst + buf * BUFB;
        size_t off = (size_t)c * KC;
#pragma unroll
        for (int i = 0; i < 4; i++) {
            cpa16(d + i * 16,         Asrc  + off + i * 8);
            cpa16(d + TILEB + i * 16, Bsrch + off + i * 8);
        }
        asm volatile("cp.async.commit_group;" ::: "memory");
    };

    stage(0, 0);
    asm volatile("cp.async.wait_group 0;" ::: "memory");
    __syncthreads();

    for (int c = 0; c < NCHUNK; c++) {
        if (c + 1 < NCHUNK) stage(c + 1, (c + 1) & 1);
        unsigned ab = a_base  + (c & 1) * BUFB;
        unsigned hb = bh_base + (c & 1) * BUFB;
#pragma unroll
        for (int ks = 0; ks < 4; ks++) {
            unsigned af[4][4], bhf[2][4];
#pragma unroll
            for (int mt = 0; mt < 4; mt++)
                ldm4(af[mt], ab + mt * (16 * SPITCHB) + ks * 32);
#pragma unroll
            for (int np = 0; np < 2; np++)
                ldm4(bhf[np], hb + np * (16 * SPITCHB) + ks * 32);
#pragma unroll
            for (int mt = 0; mt < 4; mt++)
#pragma unroll
                for (int nt = 0; nt < 4; nt++) {
                    unsigned h0 = bhf[nt >> 1][(nt & 1) * 2];
                    unsigned h1 = bhf[nt >> 1][(nt & 1) * 2 + 1];
                    mma16816(acc[mt][nt], af[mt], h0, h1);
                }
        }
        if (c + 1 < NCHUNK) {
            asm volatile("cp.async.wait_group 0;" ::: "memory");
            __syncthreads();
        }
    }

    if (!FUSE) {
#pragma unroll
        for (int mt = 0; mt < 4; mt++) {
            int r0 = bm + wm + mt * 16 + (lane >> 2);
#pragma unroll
            for (int nt = 0; nt < 4; nt++) {
                int col = bn + wn + nt * 8 + (lane & 3) * 2;
                if (r0 < M)
                    *(float2*)(g_xw + (size_t)r0 * Dq + col) =
                        make_float2(acc[mt][nt][0], acc[mt][nt][1]);
                if (r0 + 8 < M)
                    *(float2*)(g_xw + (size_t)(r0 + 8) * Dq + col) =
                        make_float2(acc[mt][nt][2], acc[mt][nt][3]);
            }
        }
    } else {
#pragma unroll
        for (int mt = 0; mt < 4; mt++) {
            float p0 = 0.f, p1 = 0.f;
#pragma unroll
            for (int nt = 0; nt < 4; nt++) {
                int col = bn + wn + nt * 8 + (lane & 3) * 2;
                float bb0 = b1v[col], bb1 = b1v[col + 1];
                float w0 = w2v[col],  w1 = w2v[col + 1];
                p0 = fmaf(fmaxf(acc[mt][nt][0] + bb0, 0.f), w0, p0);
                p0 = fmaf(fmaxf(acc[mt][nt][1] + bb1, 0.f), w1, p0);
                p1 = fmaf(fmaxf(acc[mt][nt][2] + bb0, 0.f), w0, p1);
                p1 = fmaf(fmaxf(acc[mt][nt][3] + bb1, 0.f), w1, p1);
            }
            p0 += __shfl_xor_sync(0xffffffffu, p0, 1);
            p0 += __shfl_xor_sync(0xffffffffu, p0, 2);
            p1 += __shfl_xor_sync(0xffffffffu, p1, 1);
            p1 += __shfl_xor_sync(0xffffffffu, p1, 2);
            if ((lane & 3) == 0) {
                int r0 = bm + wm + mt * 16 + (lane >> 2);
                int pc = blockIdx.x * 4 + (wid & 3);
                g_part[(size_t)r0 * 96 + pc] = p0;
                g_part[(size_t)(r0 + 8) * 96 + pc] = p1;
            }
        }
    }
}

// ---------------------------------------------------------------------------
// K0: offsets (prefix sum of 2048 sizes)
// ---------------------------------------------------------------------------
__global__ void k0_offsets(const int* __restrict__ sizes) {
    __shared__ int part[256];
    __shared__ int base[256];
    int tid = threadIdx.x;
    int loc[8];
    int ssum = 0;
#pragma unroll
    for (int i = 0; i < 8; i++) { loc[i] = ssum; ssum += sizes[tid * 8 + i]; }
    part[tid] = ssum;
    __syncthreads();
    if (tid == 0) {
        int run = 0;
        for (int i = 0; i < 256; i++) { int v = part[i]; base[i] = run; run += v; }
    }
    __syncthreads();
    int b0 = base[tid];
#pragma unroll
    for (int i = 0; i < 8; i++) g_off[tid * 8 + i] = b0 + loc[i];
}

// ---------------------------------------------------------------------------
// packed f32x2 helpers (K2)
// ---------------------------------------------------------------------------
__device__ __forceinline__ unsigned long long bcast2(float a) {
    unsigned long long r;
    asm("mov.b64 %0, {%1, %1};" : "=l"(r) : "f"(a));
    return r;
}
__device__ __forceinline__ void fma2(unsigned long long& d,
                                     unsigned long long a, unsigned long long b) {
    asm("fma.rn.f32x2 %0, %1, %2, %0;" : "+l"(d) : "l"(a), "l"(b));
}
__device__ __forceinline__ float2 upk(unsigned long long v) {
    float2 f;
    asm("mov.b64 {%0, %1}, %2;" : "=f"(f.x), "=f"(f.y) : "l"(v));
    return f;
}

// ---------------------------------------------------------------------------
// K2: per-group attention + pooling (passing since R3)
// ---------------------------------------------------------------------------
#define XS_STR  772
#define XWT_STR 34

__global__ __launch_bounds__(256) void k2_attention(
    const float* __restrict__ x, const int* __restrict__ sizes)
{
    extern __shared__ float sm[];
    float* xs  = sm;
    float* xwT = sm + 32 * XS_STR;
    float* S   = xwT + 768 * XWT_STR;
    float* att = S + 32 * 33;

    int g = blockIdx.x;
    int s = sizes[g];
    int base = g_off[g];
    int tid = threadIdx.x;

    const float4* xg = (const float4*)(x    + (size_t)base * Dq);
    const float4* wg = (const float4*)(g_xw + (size_t)base * Dq);
    int tot4 = s * (Dq / 4);
    for (int i = tid; i < tot4; i += 256) {
        int row = i / 192, d4 = i - row * 192;
        float4 v = xg[i];
        *(float4*)(xs + row * XS_STR + d4 * 4) = v;
        float4 w = wg[i];
        int d = d4 * 4;
        xwT[(d + 0) * XWT_STR + row] = w.x;
        xwT[(d + 1) * XWT_STR + row] = w.y;
        xwT[(d + 2) * XWT_STR + row] = w.z;
        xwT[(d + 3) * XWT_STR + row] = w.w;
    }
    __syncthreads();

    int ty = tid >> 4, tx = tid & 15;
    int l0 = ty * 2, m0 = tx * 2;
    if (l0 < s && m0 < s) {
        unsigned long long acc0 = 0ull, acc1 = 0ull;
        const float* xr0 = xs + l0 * XS_STR;
        const float* xr1 = xs + (l0 + 1) * XS_STR;
#pragma unroll 8
        for (int d = 0; d < Dq; d++) {
            unsigned long long wp =
                *(const unsigned long long*)&xwT[d * XWT_STR + m0];
            fma2(acc0, bcast2(xr0[d]), wp);
            fma2(acc1, bcast2(xr1[d]), wp);
        }
        float2 r0 = upk(acc0), r1 = upk(acc1);
        S[l0 * 33 + m0] = tanhf(r0.x);
        if (m0 + 1 < s) S[l0 * 33 + m0 + 1] = tanhf(r0.y);
        if (l0 + 1 < s) {
            S[(l0 + 1) * 33 + m0] = tanhf(r1.x);
            if (m0 + 1 < s) S[(l0 + 1) * 33 + m0 + 1] = tanhf(r1.y);
        }
    }
    __syncthreads();

    if (tid < 32) {
        int m = tid;
        float mx = -INFINITY;
        if (m < s)
            for (int l = 0; l < s; l++) mx = fmaxf(mx, S[l * 33 + m]);
        float wm = mx;
#pragma unroll
        for (int o = 16; o > 0; o >>= 1) wm = fmaxf(wm, __shfl_xor_sync(0xffffffffu, wm, o));
        float e = (m < s) ? expf(mx - wm) : 0.f;
        float se = e;
#pragma unroll
        for (int o = 16; o > 0; o >>= 1) se += __shfl_xor_sync(0xffffffffu, se, o);
        att[m] = e / se;
    }
    __syncthreads();

    float* outp = g_pooled + (size_t)g * Dq;
    for (int d = tid; d < Dq; d += 256) {
        float a = 0.f;
        for (int m = 0; m < s; m++) a = fmaf(att[m], xs[m * XS_STR + d], a);
        outp[d] = a;
    }
}

// ---------------------------------------------------------------------------
// K4: scores = sigmoid(sum of 96 partials + b2); margin-ranking loss.
// ---------------------------------------------------------------------------
__global__ void k4_loss(const float* __restrict__ b2, float* __restrict__ out) {
    __shared__ float sc[Gq];
    __shared__ float red[256];
    int tid = threadIdx.x;
    float bb = b2[0];
    for (int gi = tid; gi < Gq; gi += 256) {
        const float* pp = g_part + (size_t)gi * 96;
        float a = 0.f;
#pragma unroll
        for (int c = 0; c < 96; c++) a += pp[c];
        sc[gi] = 1.f / (1.f + expf(-(a + bb)));
    }
    __syncthreads();
    float s = 0.f;
    for (int idx = tid; idx < Bq * NEGq; idx += 256) {
        int b = idx / NEGq;
        int j = idx % NEGq + 1;
        float v = sc[b * 16 + j] + 0.1f - sc[b * 16];
        s += fmaxf(v, 0.f);
    }
    red[tid] = s;
    __syncthreads();
    for (int o = 128; o > 0; o >>= 1) {
        if (tid < o) red[tid] += red[tid + o];
        __syncthreads();
    }
    if (tid == 0) out[0] = red[0];
}

// ---------------------------------------------------------------------------
extern "C" void kernel_launch(void* const* d_in, const int* in_sizes, int n_in,
                              void* d_out, int out_size) {
    const float* x    = (const float*)d_in[0];
    const float* Wsfa = (const float*)d_in[1];
    const float* W1   = (const float*)d_in[2];
    const float* b1   = (const float*)d_in[3];
    const float* W2   = (const float*)d_in[4];
    const float* b2   = (const float*)d_in[5];
    const int* sizes  = (const int*)d_in[6];
    float* out = (float*)d_out;
    int N = in_sizes[0] / Dq;

    cudaFuncSetAttribute(gemm_mma<0>, cudaFuncAttributeMaxDynamicSharedMemorySize, GSMEM);
    cudaFuncSetAttribute(gemm_mma<1>, cudaFuncAttributeMaxDynamicSharedMemorySize, GSMEM);
    const int k2_smem = (32 * XS_STR + 768 * XWT_STR + 32 * 33 + 32) * 4;
    cudaFuncSetAttribute(k2_attention, cudaFuncAttributeMaxDynamicSharedMemorySize, k2_smem);

    k0_offsets<<<1, 256>>>(sizes);

    int n4x = N * Dq / 4;
    kconv<0><<<(n4x + 255) / 256, 256>>>(x, n4x);
    kconv<2><<<(Dq * Dq / 4 + 255) / 256, 256>>>(Wsfa, Dq * Dq / 4);
    kconv<3><<<(3072 * Dq / 4 + 255) / 256, 256>>>(W1, 3072 * Dq / 4);

    dim3 g1(Dq / 128, (N + 127) / 128);
    gemm_mma<0><<<g1, 256, GSMEM>>>(N, nullptr, nullptr);

    k2_attention<<<Gq, 256, k2_smem>>>(x, sizes);

    kconv<1><<<(Gq * Dq / 4 + 255) / 256, 256>>>(nullptr, Gq * Dq / 4);

    dim3 g3(3072 / 128, Gq / 128);
    gemm_mma<1><<<g3, 256, GSMEM>>>(Gq, b1, W2);

    k4_loss<<<1, 256>>>(b2, out);
}

// round 11
// speedup vs baseline: 3.4442x; 1.3319x over previous
#include <cuda_runtime.h>
#include <cuda_fp16.h>
#include <math.h>

#define Dq   768
#define Gq   2048
#define Bq   128
#define NEGq 15
#define KC   64
#define NCHUNK 12
#define MAXROWS 36864

// Static scratch. Device symbols referenced ONLY from device code.
__device__ float g_part[(size_t)Gq * 96];
__device__ int   g_off[Gq];

__device__ __half g_xh[(size_t)MAXROWS * Dq];     // x fp16
__device__ __half g_xwh[(size_t)MAXROWS * Dq];    // xw fp16 (K1 output)
__device__ __half g_wh[(size_t)Dq * Dq];          // Wsfa fp16
__device__ __half g_w1h[(size_t)3072 * Dq];       // W1 fp16
__device__ __half g_ph[(size_t)Gq * Dq];          // pooled fp16 (K2 output)

// ---------------------------------------------------------------------------
// helpers (baseline sm_80 PTX only — harness compiles for plain sm_103)
// ---------------------------------------------------------------------------
__device__ __forceinline__ unsigned smem_u32(const void* p) {
    unsigned a;
    asm("{ .reg .u64 t; cvta.to.shared.u64 t, %1; cvt.u32.u64 %0, t; }"
        : "=r"(a) : "l"(p));
    return a;
}
__device__ __forceinline__ void cpa16(unsigned d, const void* s) {
    asm volatile("cp.async.cg.shared.global [%0], [%1], 16;" :: "r"(d), "l"(s));
}
__device__ __forceinline__ void ldm4(unsigned* r, unsigned a) {
    asm volatile("ldmatrix.sync.aligned.m8n8.x4.shared.b16 {%0,%1,%2,%3}, [%4];"
                 : "=r"(r[0]), "=r"(r[1]), "=r"(r[2]), "=r"(r[3]) : "r"(a));
}
__device__ __forceinline__ void mma16816(float* d, const unsigned* a,
                                         unsigned b0, unsigned b1) {
    asm volatile("mma.sync.aligned.m16n8k16.row.col.f32.f16.f16.f32 "
                 "{%0,%1,%2,%3}, {%4,%5,%6,%7}, {%8,%9}, {%0,%1,%2,%3};"
                 : "+f"(d[0]), "+f"(d[1]), "+f"(d[2]), "+f"(d[3])
                 : "r"(a[0]), "r"(a[1]), "r"(a[2]), "r"(a[3]), "r"(b0), "r"(b1));
}

// ---------------------------------------------------------------------------
// fp32 -> fp16. DST 0: g_xh <- src ; 2: g_wh <- src ; 3: g_w1h <- src
// ---------------------------------------------------------------------------
template <int DST>
__global__ void kconv(const float* __restrict__ src, int n4)
{
    int i = blockIdx.x * blockDim.x + threadIdx.x;
    if (i >= n4) return;
    __half* hi = (DST == 0) ? g_xh : (DST == 2) ? g_wh : g_w1h;
    float4 v = ((const float4*)src)[i];
    float a[4] = {v.x, v.y, v.z, v.w};
    unsigned h[4];
#pragma unroll
    for (int j = 0; j < 4; j++)
        h[j] = (unsigned)__half_as_ushort(__float2half_rn(a[j]));
    ((uint2*)hi)[i] = make_uint2(h[0] | (h[1] << 16), h[2] | (h[3] << 16));
}

// ---------------------------------------------------------------------------
// GEMM via mma.sync fp16. CTA tile 128x128, K-chunk 64, cp.async double
// buffer, pitch 144B, 2 CTAs/SM.
// FUSE=0: A=g_xh, B=g_wh, C stored fp16 into g_xwh.
// FUSE=1: A=g_ph, B=g_w1h, fused relu(D+b1).W2 -> g_part.
// ---------------------------------------------------------------------------
#define SPITCHB 144
#define TILEB   (128 * SPITCHB)
#define BUFB    (2 * TILEB)
#define GSMEM   (2 * BUFB)        // 73728 B

template <int FUSE>
__global__ __launch_bounds__(256, 2) void gemm_mma(
    int M, const float* __restrict__ b1v, const float* __restrict__ w2v)
{
    const __half* __restrict__ Aa = FUSE ? g_ph  : g_xh;
    const __half* __restrict__ Bh = FUSE ? g_w1h : g_wh;

    extern __shared__ char smem[];
    unsigned sbase = smem_u32(smem);
    int tid = threadIdx.x, lane = tid & 31, wid = tid >> 5;
    int bm = blockIdx.y * 128, bn = blockIdx.x * 128;

    int sr = tid >> 1, sh = tid & 1;
    int arow = bm + sr; if (arow >= M) arow = M - 1;
    const __half* Asrc  = Aa + (size_t)arow * Dq + sh * 32;
    const __half* Bsrch = Bh + (size_t)(bn + sr) * Dq + sh * 32;
    unsigned sdst = sbase + sr * SPITCHB + sh * 64;

    float acc[4][4][4];
#pragma unroll
    for (int i = 0; i < 4; i++)
#pragma unroll
        for (int j = 0; j < 4; j++)
#pragma unroll
            for (int k = 0; k < 4; k++) acc[i][j][k] = 0.f;

    int wm = (wid >> 2) * 64;
    int wn = (wid & 3) * 32;
    unsigned a_base = sbase + (unsigned)(wm + (lane & 15)) * SPITCHB
                            + ((lane >> 4) << 4);
    unsigned bh_base = sbase + TILEB
        + (unsigned)(wn + (lane & 7) + ((lane >> 4) << 3)) * SPITCHB
        + (((lane >> 3) & 1) << 4);

    auto stage = [&](int c, int buf) {
        unsigned d = sdst + buf * BUFB;
        size_t off = (size_t)c * KC;
#pragma unroll
        for (int i = 0; i < 4; i++) {
            cpa16(d + i * 16,         Asrc  + off + i * 8);
            cpa16(d + TILEB + i * 16, Bsrch + off + i * 8);
        }
        asm volatile("cp.async.commit_group;" ::: "memory");
    };

    stage(0, 0);
    asm volatile("cp.async.wait_group 0;" ::: "memory");
    __syncthreads();

    for (int c = 0; c < NCHUNK; c++) {
        if (c + 1 < NCHUNK) stage(c + 1, (c + 1) & 1);
        unsigned ab = a_base  + (c & 1) * BUFB;
        unsigned hb = bh_base + (c & 1) * BUFB;
#pragma unroll
        for (int ks = 0; ks < 4; ks++) {
            unsigned af[4][4], bhf[2][4];
#pragma unroll
            for (int mt = 0; mt < 4; mt++)
                ldm4(af[mt], ab + mt * (16 * SPITCHB) + ks * 32);
#pragma unroll
            for (int np = 0; np < 2; np++)
                ldm4(bhf[np], hb + np * (16 * SPITCHB) + ks * 32);
#pragma unroll
            for (int mt = 0; mt < 4; mt++)
#pragma unroll
                for (int nt = 0; nt < 4; nt++) {
                    unsigned h0 = bhf[nt >> 1][(nt & 1) * 2];
                    unsigned h1 = bhf[nt >> 1][(nt & 1) * 2 + 1];
                    mma16816(acc[mt][nt], af[mt], h0, h1);
                }
        }
        if (c + 1 < NCHUNK) {
            asm volatile("cp.async.wait_group 0;" ::: "memory");
            __syncthreads();
        }
    }

    if (!FUSE) {
        // store C as fp16 (only consumer is K2's tensor-core S product)
#pragma unroll
        for (int mt = 0; mt < 4; mt++) {
            int r0 = bm + wm + mt * 16 + (lane >> 2);
#pragma unroll
            for (int nt = 0; nt < 4; nt++) {
                int col = bn + wn + nt * 8 + (lane & 3) * 2;
                if (r0 < M)
                    *(__half2*)(g_xwh + (size_t)r0 * Dq + col) =
                        __floats2half2_rn(acc[mt][nt][0], acc[mt][nt][1]);
                if (r0 + 8 < M)
                    *(__half2*)(g_xwh + (size_t)(r0 + 8) * Dq + col) =
                        __floats2half2_rn(acc[mt][nt][2], acc[mt][nt][3]);
            }
        }
    } else {
#pragma unroll
        for (int mt = 0; mt < 4; mt++) {
            float p0 = 0.f, p1 = 0.f;
#pragma unroll
            for (int nt = 0; nt < 4; nt++) {
                int col = bn + wn + nt * 8 + (lane & 3) * 2;
                float bb0 = b1v[col], bb1 = b1v[col + 1];
                float w0 = w2v[col],  w1 = w2v[col + 1];
                p0 = fmaf(fmaxf(acc[mt][nt][0] + bb0, 0.f), w0, p0);
                p0 = fmaf(fmaxf(acc[mt][nt][1] + bb1, 0.f), w1, p0);
                p1 = fmaf(fmaxf(acc[mt][nt][2] + bb0, 0.f), w0, p1);
                p1 = fmaf(fmaxf(acc[mt][nt][3] + bb1, 0.f), w1, p1);
            }
            p0 += __shfl_xor_sync(0xffffffffu, p0, 1);
            p0 += __shfl_xor_sync(0xffffffffu, p0, 2);
            p1 += __shfl_xor_sync(0xffffffffu, p1, 1);
            p1 += __shfl_xor_sync(0xffffffffu, p1, 2);
            if ((lane & 3) == 0) {
                int r0 = bm + wm + mt * 16 + (lane >> 2);
                int pc = blockIdx.x * 4 + (wid & 3);
                g_part[(size_t)r0 * 96 + pc] = p0;
                g_part[(size_t)(r0 + 8) * 96 + pc] = p1;
            }
        }
    }
}

// ---------------------------------------------------------------------------
// K0: offsets (prefix sum of 2048 sizes)
// ---------------------------------------------------------------------------
__global__ void k0_offsets(const int* __restrict__ sizes) {
    __shared__ int part[256];
    __shared__ int base[256];
    int tid = threadIdx.x;
    int loc[8];
    int ssum = 0;
#pragma unroll
    for (int i = 0; i < 8; i++) { loc[i] = ssum; ssum += sizes[tid * 8 + i]; }
    part[tid] = ssum;
    __syncthreads();
    if (tid == 0) {
        int run = 0;
        for (int i = 0; i < 256; i++) { int v = part[i]; base[i] = run; run += v; }
    }
    __syncthreads();
    int b0 = base[tid];
#pragma unroll
    for (int i = 0; i < 8; i++) g_off[tid * 8 + i] = b0 + loc[i];
}

// ---------------------------------------------------------------------------
// K2: per-group attention + pooling, tensor-core S product.
// One block (8 warps) per group. x and xw staged fp16 row-major, pitch 1552 B
// (4-bank row shift -> conflict-free ldmatrix, same scheme as pitch-144 GEMM).
// Warp w computes S partial over k in [w*96, w*96+96); partials tree-summed
// in smem; tanh/col-max/softmax fp32; pooled from fp16 x -> g_ph fp16.
// Rows >= s are garbage in smem but S[l][m] is only ever read for l<s, m<s.
// ---------------------------------------------------------------------------
#define P2      1552                       // bytes per fp16 row (768*2 + 16)
#define K2_XOFF 0
#define K2_WOFF (32 * P2)                  // 49664
#define K2_ROFF (2 * 32 * P2)              // 99328
#define K2_RPW  (32 * 34)                  // floats per warp partial (pitch 34)
#define K2_SOFF (K2_ROFF + 8 * K2_RPW * 4) // 99328 + 34816 = 134144
#define K2_AOFF (K2_SOFF + 32 * 33 * 4)    // 138368
#define K2SMEM  (K2_AOFF + 128)            // 138496

__global__ __launch_bounds__(256) void k2_attention(const int* __restrict__ sizes)
{
    extern __shared__ char smem[];
    unsigned sbase = smem_u32(smem);
    float* S   = (float*)(smem + K2_SOFF);
    float* att = (float*)(smem + K2_AOFF);
    float* red = (float*)(smem + K2_ROFF);

    int g = blockIdx.x;
    int s = sizes[g];
    int base = g_off[g];
    int tid = threadIdx.x, lane = tid & 31, wid = tid >> 5;

    // stage x, xw rows (fp16, 96 x 16B per row)
    const uint4* xs4 = (const uint4*)(g_xh  + (size_t)base * Dq);
    const uint4* ws4 = (const uint4*)(g_xwh + (size_t)base * Dq);
    int tot16 = s * 96;
    for (int i = tid; i < tot16; i += 256) {
        int row = i / 96, c = i - row * 96;
        *(uint4*)(smem + K2_XOFF + row * P2 + c * 16) = xs4[i];
        *(uint4*)(smem + K2_WOFF + row * P2 + c * 16) = ws4[i];
    }
    __syncthreads();

    // S partial: warp wid covers k in [wid*96, wid*96+96)
    {
        unsigned a_base = sbase + K2_XOFF + (unsigned)(lane & 15) * P2
                        + ((lane >> 4) << 4);
        unsigned b_base = sbase + K2_WOFF
                        + (unsigned)((lane & 7) + ((lane >> 4) << 3)) * P2
                        + (((lane >> 3) & 1) << 4);
        float c[2][4][4];
#pragma unroll
        for (int i = 0; i < 2; i++)
#pragma unroll
            for (int j = 0; j < 4; j++)
#pragma unroll
                for (int k = 0; k < 4; k++) c[i][j][k] = 0.f;
        unsigned wko = (unsigned)(wid * 192);     // 96 k * 2 B
#pragma unroll
        for (int ks = 0; ks < 6; ks++) {
            unsigned koff = wko + ks * 32;
            unsigned af[2][4], bf[2][4];
            ldm4(af[0], a_base + koff);
            ldm4(af[1], a_base + 16 * P2 + koff);
            ldm4(bf[0], b_base + koff);
            ldm4(bf[1], b_base + 16 * P2 + koff);
#pragma unroll
            for (int mt = 0; mt < 2; mt++)
#pragma unroll
                for (int nt = 0; nt < 4; nt++)
                    mma16816(c[mt][nt], af[mt],
                             bf[nt >> 1][(nt & 1) * 2],
                             bf[nt >> 1][(nt & 1) * 2 + 1]);
        }
        float* rw = red + wid * K2_RPW;
#pragma unroll
        for (int mt = 0; mt < 2; mt++)
#pragma unroll
            for (int nt = 0; nt < 4; nt++) {
                int row = mt * 16 + (lane >> 2);
                int col = nt * 8 + (lane & 3) * 2;
                *(float2*)&rw[row * 34 + col] =
                    make_float2(c[mt][nt][0], c[mt][nt][1]);
                *(float2*)&rw[(row + 8) * 34 + col] =
                    make_float2(c[mt][nt][2], c[mt][nt][3]);
            }
    }
    __syncthreads();

    // sum 8 partials, tanh, store S (only valid entries are ever read)
    {
        int e0 = tid * 4;
        int row = e0 >> 5, col = e0 & 31;
#pragma unroll
        for (int j = 0; j < 4; j++) {
            float v = 0.f;
#pragma unroll
            for (int w = 0; w < 8; w++)
                v += red[w * K2_RPW + row * 34 + col + j];
            if (row < s && col + j < s) S[row * 33 + col + j] = tanhf(v);
        }
    }
    __syncthreads();

    // column max over l, softmax over m (warp 0)
    if (tid < 32) {
        int m = tid;
        float mx = -INFINITY;
        if (m < s)
            for (int l = 0; l < s; l++) mx = fmaxf(mx, S[l * 33 + m]);
        float wm = mx;
#pragma unroll
        for (int o = 16; o > 0; o >>= 1) wm = fmaxf(wm, __shfl_xor_sync(0xffffffffu, wm, o));
        float e = (m < s) ? expf(mx - wm) : 0.f;
        float se = e;
#pragma unroll
        for (int o = 16; o > 0; o >>= 1) se += __shfl_xor_sync(0xffffffffu, se, o);
        att[m] = e / se;
    }
    __syncthreads();

    // pooled[d] = sum_m att[m] * x_fp16[m][d]  -> g_ph fp16
    __half* outp = g_ph + (size_t)g * Dq;
    for (int d = tid; d < Dq; d += 256) {
        float a = 0.f;
        for (int m = 0; m < s; m++) {
            __half xv = *(const __half*)(smem + K2_XOFF + m * P2 + d * 2);
            a = fmaf(att[m], __half2float(xv), a);
        }
        outp[d] = __float2half_rn(a);
    }
}

// ---------------------------------------------------------------------------
// K4: scores = sigmoid(sum of 96 partials + b2); margin-ranking loss.
// ---------------------------------------------------------------------------
__global__ void k4_loss(const float* __restrict__ b2, float* __restrict__ out) {
    __shared__ float sc[Gq];
    __shared__ float red[256];
    int tid = threadIdx.x;
    float bb = b2[0];
    for (int gi = tid; gi < Gq; gi += 256) {
        const float* pp = g_part + (size_t)gi * 96;
        float a = 0.f;
#pragma unroll
        for (int c = 0; c < 96; c++) a += pp[c];
        sc[gi] = 1.f / (1.f + expf(-(a + bb)));
    }
    __syncthreads();
    float s = 0.f;
    for (int idx = tid; idx < Bq * NEGq; idx += 256) {
        int b = idx / NEGq;
        int j = idx % NEGq + 1;
        float v = sc[b * 16 + j] + 0.1f - sc[b * 16];
        s += fmaxf(v, 0.f);
    }
    red[tid] = s;
    __syncthreads();
    for (int o = 128; o > 0; o >>= 1) {
        if (tid < o) red[tid] += red[tid + o];
        __syncthreads();
    }
    if (tid == 0) out[0] = red[0];
}

// ---------------------------------------------------------------------------
extern "C" void kernel_launch(void* const* d_in, const int* in_sizes, int n_in,
                              void* d_out, int out_size) {
    const float* x    = (const float*)d_in[0];
    const float* Wsfa = (const float*)d_in[1];
    const float* W1   = (const float*)d_in[2];
    const float* b1   = (const float*)d_in[3];
    const float* W2   = (const float*)d_in[4];
    const float* b2   = (const float*)d_in[5];
    const int* sizes  = (const int*)d_in[6];
    float* out = (float*)d_out;
    int N = in_sizes[0] / Dq;

    cudaFuncSetAttribute(gemm_mma<0>, cudaFuncAttributeMaxDynamicSharedMemorySize, GSMEM);
    cudaFuncSetAttribute(gemm_mma<1>, cudaFuncAttributeMaxDynamicSharedMemorySize, GSMEM);
    cudaFuncSetAttribute(k2_attention, cudaFuncAttributeMaxDynamicSharedMemorySize, K2SMEM);

    k0_offsets<<<1, 256>>>(sizes);

    int n4x = N * Dq / 4;
    kconv<0><<<(n4x + 255) / 256, 256>>>(x, n4x);
    kconv<2><<<(Dq * Dq / 4 + 255) / 256, 256>>>(Wsfa, Dq * Dq / 4);
    kconv<3><<<(3072 * Dq / 4 + 255) / 256, 256>>>(W1, 3072 * Dq / 4);

    dim3 g1(Dq / 128, (N + 127) / 128);
    gemm_mma<0><<<g1, 256, GSMEM>>>(N, nullptr, nullptr);

    k2_attention<<<Gq, 256, K2SMEM>>>(sizes);

    dim3 g3(3072 / 128, Gq / 128);
    gemm_mma<1><<<g3, 256, GSMEM>>>(Gq, b1, W2);

    k4_loss<<<1, 256>>>(b2, out);
}